// round 9
// baseline (speedup 1.0000x reference)
#include <cuda_runtime.h>
#include <math.h>
#include <stdint.h>

#define S_LEN  1024
#define HDIM   1024
#define NTOK   4096            // B*S
#define NHEADS 16
#define DHEAD  64
#define PATHS  16

// ---------------- scratch (static __device__, no allocation) ----------------
__device__ float4 g_x_   [NTOK*HDIM/4];        // ln1 out
__device__ float4 g_qkv_ [NTOK*3*HDIM/4];      // qkv
__device__ float4 g_ctx_ [NTOK*HDIM/4];        // attention context
__device__ float4 g_h_   [NTOK*HDIM/4];        // residual-1 out
__device__ float4 g_x2_  [NTOK*HDIM/4];        // ln2 out
__device__ float4 g_r1_  [NTOK*256/4];         // router hidden
__device__ float4 g_w_   [NTOK*PATHS/4];       // pathway weights
__device__ float4 g_int_ [(long long)PATHS*NTOK*256/4]; // pathway intermediates

// ---------------- LayerNorm (one block per row of 1024) ----------------
__global__ __launch_bounds__(256) void ln_kernel(
    const float* __restrict__ x, const float* __restrict__ gamma,
    const float* __restrict__ beta, float* __restrict__ y)
{
    long long row = blockIdx.x;
    const float* xr = x + row * HDIM;
    float* yr = y + row * HDIM;
    int tid = threadIdx.x;

    float4 v = *(const float4*)&xr[tid * 4];
    float s  = v.x + v.y + v.z + v.w;
    float ss = v.x*v.x + v.y*v.y + v.z*v.z + v.w*v.w;
    #pragma unroll
    for (int o = 16; o; o >>= 1) {
        s  += __shfl_xor_sync(0xffffffffu, s,  o);
        ss += __shfl_xor_sync(0xffffffffu, ss, o);
    }
    __shared__ float rs[8], rss[8];
    int w = tid >> 5, ln = tid & 31;
    if (ln == 0) { rs[w] = s; rss[w] = ss; }
    __syncthreads();
    s = 0.f; ss = 0.f;
    #pragma unroll
    for (int i = 0; i < 8; i++) { s += rs[i]; ss += rss[i]; }

    float mean = s * (1.0f / HDIM);
    float var  = ss * (1.0f / HDIM) - mean * mean;
    float inv  = rsqrtf(var + 1e-5f);

    float4 g = *(const float4*)&gamma[tid * 4];
    float4 b = *(const float4*)&beta[tid * 4];
    float4 o;
    o.x = (v.x - mean) * inv * g.x + b.x;
    o.y = (v.y - mean) * inv * g.y + b.y;
    o.z = (v.z - mean) * inv * g.z + b.z;
    o.w = (v.w - mean) * inv * g.w + b.w;
    *(float4*)&yr[tid * 4] = o;
}

// ---------------- tf32 tensor-core GEMM: C[M,N] = A[M,K] @ B[N,K]^T ---------
// BM=128, BN=64, BK=16, 256 threads (8 warps), warp tile 32x32 via
// mma.sync.m16n8k8.row.col.f32.tf32.tf32.f32.
// Smem columns are PERMUTED within each 32-wide group (mm -> (mm%8)*4 + mm/8)
// so each thread's 4 fragment rows/cols {g, g+8, g+16, g+24} form one float4.
// EPI: 0=bias  1=bias+res  2=bias+relu  3=gelu(bias)  4=res + (acc+bias)*w[row,z]
__device__ __forceinline__ float gelu_tanh(float x) {
    float t = tanhf(0.7978845608028654f * (x + 0.044715f * x * x * x));
    return 0.5f * x * (1.0f + t);
}

__device__ __forceinline__ uint32_t f2tf32(float x) {
    uint32_t r;
    asm("cvt.rna.tf32.f32 %0, %1;" : "=r"(r) : "f"(x));
    return r;
}

__device__ __forceinline__ void mma_tf32(float c[4], const uint32_t a[4], const uint32_t b[2]) {
    asm volatile(
        "mma.sync.aligned.m16n8k8.row.col.f32.tf32.tf32.f32 "
        "{%0,%1,%2,%3}, {%4,%5,%6,%7}, {%8,%9}, {%0,%1,%2,%3};\n"
        : "+f"(c[0]), "+f"(c[1]), "+f"(c[2]), "+f"(c[3])
        : "r"(a[0]), "r"(a[1]), "r"(a[2]), "r"(a[3]), "r"(b[0]), "r"(b[1]));
}

// permute within 32-group: keep group base, map mm%32 -> (mm%8)*4 + (mm%32)/8
__device__ __forceinline__ int permc(int m) {
    return (m & ~31) | ((m & 7) << 2) | ((m & 31) >> 3);
}

template<int EPI>
__global__ __launch_bounds__(256) void tgemm_kernel(
    const float* __restrict__ A, int lda, long long aZ,
    const float* __restrict__ B, int ldb, long long bZ,
    float* __restrict__ C, int ldc, long long cZ,
    int K,
    const float* __restrict__ bias, int biasZ,
    const float* __restrict__ res, int resZ, int ldres,
    const float* __restrict__ wvec)
{
    const int z = blockIdx.z;
    A += (long long)z * aZ;
    B += (long long)z * bZ;
    C += (long long)z * cZ;
    bias += (long long)z * biasZ;
    if (EPI == 1 || EPI == 4) res += (long long)z * resZ;

    __shared__ __align__(16) uint32_t As[16][136];
    __shared__ __align__(16) uint32_t Bs[16][72];

    const int tid  = threadIdx.x;
    const int warp = tid >> 5;
    const int lane = tid & 31;
    const int g = lane >> 2;       // groupID
    const int t = lane & 3;        // threadID_in_group
    const int wm = (warp & 3) * 32;    // warp m-offset
    const int wn = (warp >> 2) * 32;   // warp n-offset
    const int bm = blockIdx.y * 128, bn = blockIdx.x * 64;

    const int lr  = tid >> 2;          // 0..63
    const int lc4 = (tid & 3) * 4;     // 0,4,8,12
    const int plr = permc(lr);         // permuted column for stores

    float acc[2][4][4];
    #pragma unroll
    for (int i = 0; i < 2; i++)
        #pragma unroll
        for (int j = 0; j < 4; j++)
            #pragma unroll
            for (int q = 0; q < 4; q++) acc[i][j][q] = 0.f;

    // pipeline: global-load regs for tile k0, store to smem, prefetch k0+16, compute
    float4 a0 = *(const float4*)&A[(long long)(bm + lr)      * lda + lc4];
    float4 a1 = *(const float4*)&A[(long long)(bm + 64 + lr) * lda + lc4];
    float4 b0 = *(const float4*)&B[(long long)(bn + lr)      * ldb + lc4];

    for (int k0 = 0; k0 < K; k0 += 16) {
        if (k0) __syncthreads();
        As[lc4+0][plr]    = f2tf32(a0.x); As[lc4+1][plr]    = f2tf32(a0.y);
        As[lc4+2][plr]    = f2tf32(a0.z); As[lc4+3][plr]    = f2tf32(a0.w);
        As[lc4+0][64+plr] = f2tf32(a1.x); As[lc4+1][64+plr] = f2tf32(a1.y);
        As[lc4+2][64+plr] = f2tf32(a1.z); As[lc4+3][64+plr] = f2tf32(a1.w);
        Bs[lc4+0][plr]    = f2tf32(b0.x); Bs[lc4+1][plr]    = f2tf32(b0.y);
        Bs[lc4+2][plr]    = f2tf32(b0.z); Bs[lc4+3][plr]    = f2tf32(b0.w);
        __syncthreads();

        if (k0 + 16 < K) {
            a0 = *(const float4*)&A[(long long)(bm + lr)      * lda + k0 + 16 + lc4];
            a1 = *(const float4*)&A[(long long)(bm + 64 + lr) * lda + k0 + 16 + lc4];
            b0 = *(const float4*)&B[(long long)(bn + lr)      * ldb + k0 + 16 + lc4];
        }

        #pragma unroll
        for (int ks = 0; ks < 16; ks += 8) {
            // element e of each float4 = original row/col (8e + g) within warp group
            uint4 aL0 = *(const uint4*)&As[ks + t    ][wm + g * 4];
            uint4 aL1 = *(const uint4*)&As[ks + t + 4][wm + g * 4];
            uint4 bL0 = *(const uint4*)&Bs[ks + t    ][wn + g * 4];
            uint4 bL1 = *(const uint4*)&Bs[ks + t + 4][wn + g * 4];

            uint32_t af[2][4], bf[4][2];
            af[0][0] = aL0.x; af[0][1] = aL0.y; af[0][2] = aL1.x; af[0][3] = aL1.y;
            af[1][0] = aL0.z; af[1][1] = aL0.w; af[1][2] = aL1.z; af[1][3] = aL1.w;
            bf[0][0] = bL0.x; bf[0][1] = bL1.x;
            bf[1][0] = bL0.y; bf[1][1] = bL1.y;
            bf[2][0] = bL0.z; bf[2][1] = bL1.z;
            bf[3][0] = bL0.w; bf[3][1] = bL1.w;

            #pragma unroll
            for (int i = 0; i < 2; i++)
                #pragma unroll
                for (int j = 0; j < 4; j++)
                    mma_tf32(acc[i][j], af[i], bf[j]);
        }
    }

    // epilogue: thread holds rows (bm+wm+16i+g) and (+8), cols (bn+wn+8j+2t, +1)
    #pragma unroll
    for (int i = 0; i < 2; i++) {
        const long long r0 = bm + wm + 16*i + g;
        const long long r1 = r0 + 8;
        float w0 = 0.f, w1 = 0.f;
        if (EPI == 4) { w0 = wvec[r0 * PATHS + z]; w1 = wvec[r1 * PATHS + z]; }
        #pragma unroll
        for (int j = 0; j < 4; j++) {
            const int col = bn + wn + 8*j + 2*t;
            const float bx = bias[col], by = bias[col + 1];
            float v0 = acc[i][j][0] + bx, v1 = acc[i][j][1] + by;   // row r0
            float v2 = acc[i][j][2] + bx, v3 = acc[i][j][3] + by;   // row r1
            if (EPI == 1) {
                float2 q0 = *(const float2*)&res[r0 * ldres + col];
                float2 q1 = *(const float2*)&res[r1 * ldres + col];
                v0 += q0.x; v1 += q0.y; v2 += q1.x; v3 += q1.y;
            }
            if (EPI == 2) { v0 = fmaxf(v0,0.f); v1 = fmaxf(v1,0.f); v2 = fmaxf(v2,0.f); v3 = fmaxf(v3,0.f); }
            if (EPI == 3) { v0 = gelu_tanh(v0); v1 = gelu_tanh(v1); v2 = gelu_tanh(v2); v3 = gelu_tanh(v3); }
            if (EPI == 4) {
                float2 q0 = *(const float2*)&res[r0 * ldres + col];
                float2 q1 = *(const float2*)&res[r1 * ldres + col];
                v0 = q0.x + v0 * w0; v1 = q0.y + v1 * w0;
                v2 = q1.x + v2 * w1; v3 = q1.y + v3 * w1;
            }
            *(float2*)&C[r0 * ldc + col] = make_float2(v0, v1);
            *(float2*)&C[r1 * ldc + col] = make_float2(v2, v3);
        }
    }
}

// ---------------- flash attention: 64 q-rows per block, Dh=64 ----------------
__global__ __launch_bounds__(256) void attn_kernel(
    const float* __restrict__ qkv, float* __restrict__ ctx)
{
    const int qb = blockIdx.x;     // 0..15 (q tile)
    const int h  = blockIdx.y;     // head
    const int b  = blockIdx.z;     // batch
    const float* base = qkv + (long long)b * S_LEN * 3 * HDIM;

    __shared__ __align__(16) float Qs[64][64];   // [d][qr], pre-scaled
    __shared__ __align__(16) float KP[64][64];   // K as [d][kc], then P as [kc][qr]
    __shared__ __align__(16) float Vs[64][64];   // [kv][d]

    const int tid = threadIdx.x;
    const int tx = tid & 15, ty = tid >> 4;

    // load Q (scaled by 1/sqrt(64)=0.125), transposed
    for (int i = tid; i < 64 * 16; i += 256) {
        int qr = i >> 4, d4 = (i & 15) * 4;
        float4 v = *(const float4*)&base[(long long)(qb * 64 + qr) * (3 * HDIM) + h * DHEAD + d4];
        Qs[d4+0][qr] = v.x * 0.125f; Qs[d4+1][qr] = v.y * 0.125f;
        Qs[d4+2][qr] = v.z * 0.125f; Qs[d4+3][qr] = v.w * 0.125f;
    }

    float m[4], l[4], o[4][4];
    #pragma unroll
    for (int i = 0; i < 4; i++) {
        m[i] = -1e30f; l[i] = 0.f;
        #pragma unroll
        for (int j = 0; j < 4; j++) o[i][j] = 0.f;
    }

    for (int kb = 0; kb <= qb; kb++) {
        __syncthreads();   // previous iteration's reads of KP/Vs are done
        for (int i = tid; i < 64 * 16; i += 256) {
            int kc = i >> 4, d4 = (i & 15) * 4;
            long long rowoff = (long long)(kb * 64 + kc) * (3 * HDIM) + h * DHEAD + d4;
            float4 kv = *(const float4*)&base[rowoff + HDIM];
            KP[d4+0][kc] = kv.x; KP[d4+1][kc] = kv.y; KP[d4+2][kc] = kv.z; KP[d4+3][kc] = kv.w;
            float4 vv = *(const float4*)&base[rowoff + 2 * HDIM];
            *(float4*)&Vs[kc][d4] = vv;
        }
        __syncthreads();

        // S = Q K^T
        float s[4][4];
        #pragma unroll
        for (int i = 0; i < 4; i++)
            #pragma unroll
            for (int j = 0; j < 4; j++) s[i][j] = 0.f;
        #pragma unroll 16
        for (int kk = 0; kk < 64; kk++) {
            float4 aq = *(const float4*)&Qs[kk][ty * 4];
            float4 bk = *(const float4*)&KP[kk][tx * 4];
            float ar[4] = {aq.x, aq.y, aq.z, aq.w};
            float br[4] = {bk.x, bk.y, bk.z, bk.w};
            #pragma unroll
            for (int i = 0; i < 4; i++)
                #pragma unroll
                for (int j = 0; j < 4; j++)
                    s[i][j] += ar[i] * br[j];
        }

        // causal mask on diagonal tile
        if (kb == qb) {
            #pragma unroll
            for (int i = 0; i < 4; i++) {
                int qg = ty * 4 + i;
                #pragma unroll
                for (int j = 0; j < 4; j++)
                    if (tx * 4 + j > qg) s[i][j] = -1e9f;
            }
        }

        // online softmax: per-row stats shared by the 16 tx-lanes of each ty group
        #pragma unroll
        for (int i = 0; i < 4; i++) {
            float rm = fmaxf(fmaxf(s[i][0], s[i][1]), fmaxf(s[i][2], s[i][3]));
            #pragma unroll
            for (int off = 1; off < 16; off <<= 1)
                rm = fmaxf(rm, __shfl_xor_sync(0xffffffffu, rm, off, 16));
            float mnew = fmaxf(m[i], rm);
            float scale = __expf(m[i] - mnew);
            m[i] = mnew;
            float rsum = 0.f;
            #pragma unroll
            for (int j = 0; j < 4; j++) {
                float p = __expf(s[i][j] - mnew);
                s[i][j] = p; rsum += p;
            }
            #pragma unroll
            for (int off = 1; off < 16; off <<= 1)
                rsum += __shfl_xor_sync(0xffffffffu, rsum, off, 16);
            l[i] = l[i] * scale + rsum;
            #pragma unroll
            for (int j = 0; j < 4; j++) o[i][j] *= scale;
        }

        __syncthreads();   // everyone finished reading KP (K data)
        #pragma unroll
        for (int i = 0; i < 4; i++)
            #pragma unroll
            for (int j = 0; j < 4; j++)
                KP[tx * 4 + j][ty * 4 + i] = s[i][j];
        __syncthreads();

        // O += P V
        #pragma unroll 16
        for (int kk = 0; kk < 64; kk++) {
            float4 ap = *(const float4*)&KP[kk][ty * 4];
            float4 bv = *(const float4*)&Vs[kk][tx * 4];
            float ar[4] = {ap.x, ap.y, ap.z, ap.w};
            float br[4] = {bv.x, bv.y, bv.z, bv.w};
            #pragma unroll
            for (int i = 0; i < 4; i++)
                #pragma unroll
                for (int j = 0; j < 4; j++)
                    o[i][j] += ar[i] * br[j];
        }
    }

    #pragma unroll
    for (int i = 0; i < 4; i++) {
        float inv = 1.0f / l[i];
        long long t = (long long)b * S_LEN + qb * 64 + ty * 4 + i;
        #pragma unroll
        for (int j = 0; j < 4; j++)
            ctx[t * HDIM + h * DHEAD + tx * 4 + j] = o[i][j] * inv;
    }
}

// ---------------- router: GEMV(16x256) + softmax + top-4 + renorm ------------
__global__ __launch_bounds__(128) void router_kernel(
    const float* __restrict__ r1, const float* __restrict__ Wr2,
    const float* __restrict__ br2, float* __restrict__ wout)
{
    int t = blockIdx.x;
    int tid = threadIdx.x;
    int p = tid >> 3, lane8 = tid & 7;

    const float4* a4 = (const float4*)(r1 + (long long)t * 256);
    const float4* w4 = (const float4*)(Wr2 + (long long)p * 256);
    float s = 0.f;
    #pragma unroll
    for (int j = 0; j < 8; j++) {
        float4 av = a4[lane8 * 8 + j];
        float4 wv = w4[lane8 * 8 + j];
        s += av.x * wv.x + av.y * wv.y + av.z * wv.z + av.w * wv.w;
    }
    #pragma unroll
    for (int o = 1; o < 8; o <<= 1) s += __shfl_xor_sync(0xffffffffu, s, o, 8);

    __shared__ float rv[16];
    if (lane8 == 0) rv[p] = s + br2[p];
    __syncthreads();

    if (tid == 0) {
        float pr[16];
        float vmax = rv[0];
        #pragma unroll
        for (int i = 1; i < 16; i++) vmax = fmaxf(vmax, rv[i]);
        float sum = 0.f;
        #pragma unroll
        for (int i = 0; i < 16; i++) { pr[i] = __expf(rv[i] - vmax); sum += pr[i]; }
        float inv = 1.0f / sum;
        #pragma unroll
        for (int i = 0; i < 16; i++) pr[i] *= inv;

        bool sel[16];
        #pragma unroll
        for (int i = 0; i < 16; i++) sel[i] = false;
        float ssum = 0.f;
        for (int k = 0; k < 4; k++) {
            int best = 0; float bv = -1.0f;
            for (int i = 0; i < 16; i++)
                if (!sel[i] && pr[i] > bv) { bv = pr[i]; best = i; }
            sel[best] = true; ssum += bv;
        }
        float dinv = 1.0f / (ssum + 1e-8f);
        for (int i = 0; i < 16; i++)
            wout[(long long)t * 16 + i] = sel[i] ? pr[i] * dinv : 0.f;
    }
}

// ---------------- launch ----------------
extern "C" void kernel_launch(void* const* d_in, const int* in_sizes, int n_in,
                              void* d_out, int out_size)
{
    const float* hidden = (const float*)d_in[0];
    const float* ln1w   = (const float*)d_in[1];
    const float* ln1b   = (const float*)d_in[2];
    const float* Wqkv   = (const float*)d_in[3];
    const float* bqkv   = (const float*)d_in[4];
    const float* Wo     = (const float*)d_in[5];
    const float* bo     = (const float*)d_in[6];
    const float* ln2w   = (const float*)d_in[7];
    const float* ln2b   = (const float*)d_in[8];
    const float* Wr1    = (const float*)d_in[9];
    const float* br1    = (const float*)d_in[10];
    const float* Wr2    = (const float*)d_in[11];
    const float* br2    = (const float*)d_in[12];
    const float* W1     = (const float*)d_in[13];
    const float* b1     = (const float*)d_in[14];
    const float* W2     = (const float*)d_in[15];
    const float* b2     = (const float*)d_in[16];
    float* out = (float*)d_out;

    float *x, *qkv, *ctx, *h, *x2, *r1, *wv, *inter;
    cudaGetSymbolAddress((void**)&x,     g_x_);
    cudaGetSymbolAddress((void**)&qkv,   g_qkv_);
    cudaGetSymbolAddress((void**)&ctx,   g_ctx_);
    cudaGetSymbolAddress((void**)&h,     g_h_);
    cudaGetSymbolAddress((void**)&x2,    g_x2_);
    cudaGetSymbolAddress((void**)&r1,    g_r1_);
    cudaGetSymbolAddress((void**)&wv,    g_w_);
    cudaGetSymbolAddress((void**)&inter, g_int_);

    // 1) LN1
    ln_kernel<<<NTOK, 256>>>(hidden, ln1w, ln1b, x);
    // 2) QKV = x @ Wqkv^T + bqkv            [4096 x 3072]
    tgemm_kernel<0><<<dim3(3072/64, NTOK/128, 1), 256>>>(
        x, HDIM, 0, Wqkv, HDIM, 0, qkv, 3*HDIM, 0, HDIM,
        bqkv, 0, nullptr, 0, 0, nullptr);
    // 3) causal attention -> ctx
    attn_kernel<<<dim3(S_LEN/64, NHEADS, 4), 256>>>(qkv, ctx);
    // 4) h = hidden + ctx @ Wo^T + bo
    tgemm_kernel<1><<<dim3(HDIM/64, NTOK/128, 1), 256>>>(
        ctx, HDIM, 0, Wo, HDIM, 0, h, HDIM, 0, HDIM,
        bo, 0, hidden, 0, HDIM, nullptr);
    // 5) LN2
    ln_kernel<<<NTOK, 256>>>(h, ln2w, ln2b, x2);
    // 6) r1 = relu(x2 @ Wr1^T + br1)        [4096 x 256]
    tgemm_kernel<2><<<dim3(256/64, NTOK/128, 1), 256>>>(
        x2, HDIM, 0, Wr1, HDIM, 0, r1, 256, 0, HDIM,
        br1, 0, nullptr, 0, 0, nullptr);
    // 7) router logits + softmax + top-4 + renorm -> w [4096 x 16]
    router_kernel<<<NTOK, 128>>>(r1, Wr2, br2, wv);
    // 8) inter_p = gelu(x2_p @ W1b_p^T + b1_p)   (z = pathway)
    tgemm_kernel<3><<<dim3(256/64, NTOK/128, PATHS), 256>>>(
        x2, HDIM, 64, W1, HDIM, (long long)256*HDIM + 64,
        inter, 256, (long long)NTOK*256, 64,
        b1, 256, nullptr, 0, 0, nullptr);
    // 9) out = h + (inter_p @ W2b_p^T + b2_p) * w[:,p]   (z = pathway)
    tgemm_kernel<4><<<dim3(1, NTOK/128, PATHS), 256>>>(
        inter, 256, (long long)NTOK*256, W2, 4096, (long long)64*4096 + 256,
        out, HDIM, 64, 256,
        b2, 64, h, 64, HDIM, wv);
}

// round 12
// speedup vs baseline: 1.0232x; 1.0232x over previous
#include <cuda_runtime.h>
#include <math.h>
#include <stdint.h>

#define S_LEN  1024
#define HDIM   1024
#define NTOK   4096            // B*S
#define NHEADS 16
#define DHEAD  64
#define PATHS  16
#define STAGES 3

// ---------------- scratch (static __device__, no allocation) ----------------
__device__ float4 g_x_   [NTOK*HDIM/4];        // ln1 out
__device__ float4 g_qkv_ [NTOK*3*HDIM/4];      // qkv
__device__ float4 g_ctx_ [NTOK*HDIM/4];        // attention context
__device__ float4 g_h_   [NTOK*HDIM/4];        // residual-1 out
__device__ float4 g_x2_  [NTOK*HDIM/4];        // ln2 out
__device__ float4 g_r1_  [NTOK*256/4];         // router hidden
__device__ float4 g_w_   [NTOK*PATHS/4];       // pathway weights
__device__ float4 g_int_ [(long long)PATHS*NTOK*256/4]; // pathway intermediates

// ---------------- LayerNorm (one block per row of 1024) ----------------
__global__ __launch_bounds__(256) void ln_kernel(
    const float* __restrict__ x, const float* __restrict__ gamma,
    const float* __restrict__ beta, float* __restrict__ y)
{
    long long row = blockIdx.x;
    const float* xr = x + row * HDIM;
    float* yr = y + row * HDIM;
    int tid = threadIdx.x;

    float4 v = *(const float4*)&xr[tid * 4];
    float s  = v.x + v.y + v.z + v.w;
    float ss = v.x*v.x + v.y*v.y + v.z*v.z + v.w*v.w;
    #pragma unroll
    for (int o = 16; o; o >>= 1) {
        s  += __shfl_xor_sync(0xffffffffu, s,  o);
        ss += __shfl_xor_sync(0xffffffffu, ss, o);
    }
    __shared__ float rs[8], rss[8];
    int w = tid >> 5, ln = tid & 31;
    if (ln == 0) { rs[w] = s; rss[w] = ss; }
    __syncthreads();
    s = 0.f; ss = 0.f;
    #pragma unroll
    for (int i = 0; i < 8; i++) { s += rs[i]; ss += rss[i]; }

    float mean = s * (1.0f / HDIM);
    float var  = ss * (1.0f / HDIM) - mean * mean;
    float inv  = rsqrtf(var + 1e-5f);

    float4 g = *(const float4*)&gamma[tid * 4];
    float4 b = *(const float4*)&beta[tid * 4];
    float4 o;
    o.x = (v.x - mean) * inv * g.x + b.x;
    o.y = (v.y - mean) * inv * g.y + b.y;
    o.z = (v.z - mean) * inv * g.z + b.z;
    o.w = (v.w - mean) * inv * g.w + b.w;
    *(float4*)&yr[tid * 4] = o;
}

// ---------------- tf32 tensor-core GEMM with cp.async pipeline --------------
// C[M,N] = A[M,K] @ B[N,K]^T.  BM=128, BN=64, BK=16, 256 threads (8 warps),
// warp tile 32x32 via mma.sync.m16n8k8.row.col.f32.tf32.tf32.f32.
// 3-stage cp.async (LDGSTS) pipeline; smem layout [k/4][row][k%4] so each
// global 16B chunk is smem-contiguous. MMA consumes raw fp32 bits (HW
// truncation to tf32).
// EPI: 0=bias  1=bias+res  2=bias+relu  3=gelu(bias)  4=res + (acc+bias)*w[row,z]
__device__ __forceinline__ float gelu_tanh(float x) {
    float t = tanhf(0.7978845608028654f * (x + 0.044715f * x * x * x));
    return 0.5f * x * (1.0f + t);
}

__device__ __forceinline__ void mma_tf32(float c[4], const uint32_t a[4], const uint32_t b[2]) {
    asm volatile(
        "mma.sync.aligned.m16n8k8.row.col.f32.tf32.tf32.f32 "
        "{%0,%1,%2,%3}, {%4,%5,%6,%7}, {%8,%9}, {%0,%1,%2,%3};\n"
        : "+f"(c[0]), "+f"(c[1]), "+f"(c[2]), "+f"(c[3])
        : "r"(a[0]), "r"(a[1]), "r"(a[2]), "r"(a[3]), "r"(b[0]), "r"(b[1]));
}

__device__ __forceinline__ void cp16(uint32_t dst, const void* src) {
    asm volatile("cp.async.cg.shared.global [%0], [%1], 16;\n" :: "r"(dst), "l"(src));
}
#define CP_COMMIT() asm volatile("cp.async.commit_group;\n" ::)
#define CP_WAIT1()  asm volatile("cp.async.wait_group 1;\n" ::)

template<int EPI>
__global__ __launch_bounds__(256) void tgemm_kernel(
    const float* __restrict__ A, int lda, long long aZ,
    const float* __restrict__ B, int ldb, long long bZ,
    float* __restrict__ C, int ldc, long long cZ,
    int K,
    const float* __restrict__ bias, int biasZ,
    const float* __restrict__ res, int resZ, int ldres,
    const float* __restrict__ wvec)
{
    const int z = blockIdx.z;
    A += (long long)z * aZ;
    B += (long long)z * bZ;
    C += (long long)z * cZ;
    bias += (long long)z * biasZ;
    if (EPI == 1 || EPI == 4) res += (long long)z * resZ;

    // [stage][chunk(k/4)][row][k%4]
    __shared__ __align__(16) uint32_t As[STAGES][4][128][4];   // 24 KB
    __shared__ __align__(16) uint32_t Bs[STAGES][4][64][4];    // 12 KB

    const int tid  = threadIdx.x;
    const int warp = tid >> 5;
    const int lane = tid & 31;
    const int g = lane >> 2;           // groupID
    const int t = lane & 3;            // threadID_in_group
    const int wm = (warp & 3) * 32;    // warp m-offset
    const int wn = (warp >> 2) * 32;   // warp n-offset
    const int bm = blockIdx.y * 128, bn = blockIdx.x * 64;

    const uint32_t As_addr = (uint32_t)__cvta_generic_to_shared(&As[0][0][0][0]);
    const uint32_t Bs_addr = (uint32_t)__cvta_generic_to_shared(&Bs[0][0][0][0]);

    // copy-role indices (16B chunks)
    const int ar0 = tid >> 2,  ac0 = tid & 3;            // A chunk 0: rows 0..63
    const int ar1 = ar0 + 64,  ac1 = ac0;                // A chunk 1: rows 64..127
    const int br0 = tid >> 2,  bc0 = tid & 3;            // B: rows 0..63

    float acc[2][4][4];
    #pragma unroll
    for (int i = 0; i < 2; i++)
        #pragma unroll
        for (int j = 0; j < 4; j++)
            #pragma unroll
            for (int q = 0; q < 4; q++) acc[i][j][q] = 0.f;

    const int NT = K >> 4;

    // prologue: fill stages 0..STAGES-2
    #pragma unroll
    for (int s = 0; s < STAGES - 1; ++s) {
        const int k0 = s << 4;
        cp16(As_addr + (((s*4 + ac0)*128 + ar0) << 4),
             &A[(long long)(bm + ar0) * lda + k0 + (ac0 << 2)]);
        cp16(As_addr + (((s*4 + ac1)*128 + ar1) << 4),
             &A[(long long)(bm + ar1) * lda + k0 + (ac1 << 2)]);
        cp16(Bs_addr + (((s*4 + bc0)*64 + br0) << 4),
             &B[(long long)(bn + br0) * ldb + k0 + (bc0 << 2)]);
        CP_COMMIT();
    }

    int st = 0;
    for (int it = 0; it < NT; ++it) {
        CP_WAIT1();
        __syncthreads();

        const int nx = it + STAGES - 1;
        if (nx < NT) {
            const int ns = (st + STAGES - 1) % STAGES;
            const int k0 = nx << 4;
            cp16(As_addr + (((ns*4 + ac0)*128 + ar0) << 4),
                 &A[(long long)(bm + ar0) * lda + k0 + (ac0 << 2)]);
            cp16(As_addr + (((ns*4 + ac1)*128 + ar1) << 4),
                 &A[(long long)(bm + ar1) * lda + k0 + (ac1 << 2)]);
            cp16(Bs_addr + (((ns*4 + bc0)*64 + br0) << 4),
                 &B[(long long)(bn + br0) * ldb + k0 + (bc0 << 2)]);
        }
        CP_COMMIT();

        #pragma unroll
        for (int ks = 0; ks < 16; ks += 8) {
            const int c1 = ks >> 2;      // chunk of k = ks + t   (t < 4)
            const int c2 = c1 + 1;       // chunk of k = ks + t + 4
            uint32_t af[2][4], bf[4][2];
            #pragma unroll
            for (int i = 0; i < 2; i++) {
                af[i][0] = As[st][c1][wm + 16*i + g    ][t];
                af[i][1] = As[st][c1][wm + 16*i + g + 8][t];
                af[i][2] = As[st][c2][wm + 16*i + g    ][t];
                af[i][3] = As[st][c2][wm + 16*i + g + 8][t];
            }
            #pragma unroll
            for (int j = 0; j < 4; j++) {
                bf[j][0] = Bs[st][c1][wn + 8*j + g][t];
                bf[j][1] = Bs[st][c2][wn + 8*j + g][t];
            }
            #pragma unroll
            for (int i = 0; i < 2; i++)
                #pragma unroll
                for (int j = 0; j < 4; j++)
                    mma_tf32(acc[i][j], af[i], bf[j]);
        }

        st = (st + 1 == STAGES) ? 0 : st + 1;
    }

    // epilogue: thread holds rows (bm+wm+16i+g) and (+8), cols (bn+wn+8j+2t, +1)
    #pragma unroll
    for (int i = 0; i < 2; i++) {
        const long long r0 = bm + wm + 16*i + g;
        const long long r1 = r0 + 8;
        float w0 = 0.f, w1 = 0.f;
        if (EPI == 4) { w0 = wvec[r0 * PATHS + z]; w1 = wvec[r1 * PATHS + z]; }
        #pragma unroll
        for (int j = 0; j < 4; j++) {
            const int col = bn + wn + 8*j + 2*t;
            const float bx = bias[col], by = bias[col + 1];
            float v0 = acc[i][j][0] + bx, v1 = acc[i][j][1] + by;   // row r0
            float v2 = acc[i][j][2] + bx, v3 = acc[i][j][3] + by;   // row r1
            if (EPI == 1) {
                float2 q0 = *(const float2*)&res[r0 * ldres + col];
                float2 q1 = *(const float2*)&res[r1 * ldres + col];
                v0 += q0.x; v1 += q0.y; v2 += q1.x; v3 += q1.y;
            }
            if (EPI == 2) { v0 = fmaxf(v0,0.f); v1 = fmaxf(v1,0.f); v2 = fmaxf(v2,0.f); v3 = fmaxf(v3,0.f); }
            if (EPI == 3) { v0 = gelu_tanh(v0); v1 = gelu_tanh(v1); v2 = gelu_tanh(v2); v3 = gelu_tanh(v3); }
            if (EPI == 4) {
                float2 q0 = *(const float2*)&res[r0 * ldres + col];
                float2 q1 = *(const float2*)&res[r1 * ldres + col];
                v0 = q0.x + v0 * w0; v1 = q0.y + v1 * w0;
                v2 = q1.x + v2 * w1; v3 = q1.y + v3 * w1;
            }
            *(float2*)&C[r0 * ldc + col] = make_float2(v0, v1);
            *(float2*)&C[r1 * ldc + col] = make_float2(v2, v3);
        }
    }
}

// ---------------- flash attention: 64 q-rows per block, Dh=64 ----------------
__global__ __launch_bounds__(256) void attn_kernel(
    const float* __restrict__ qkv, float* __restrict__ ctx)
{
    const int qb = blockIdx.x;     // 0..15 (q tile)
    const int h  = blockIdx.y;     // head
    const int b  = blockIdx.z;     // batch
    const float* base = qkv + (long long)b * S_LEN * 3 * HDIM;

    __shared__ __align__(16) float Qs[64][64];   // [d][qr], pre-scaled
    __shared__ __align__(16) float KP[64][64];   // K as [d][kc], then P as [kc][qr]
    __shared__ __align__(16) float Vs[64][64];   // [kv][d]

    const int tid = threadIdx.x;
    const int tx = tid & 15, ty = tid >> 4;

    // load Q (scaled by 1/sqrt(64)=0.125), transposed
    for (int i = tid; i < 64 * 16; i += 256) {
        int qr = i >> 4, d4 = (i & 15) * 4;
        float4 v = *(const float4*)&base[(long long)(qb * 64 + qr) * (3 * HDIM) + h * DHEAD + d4];
        Qs[d4+0][qr] = v.x * 0.125f; Qs[d4+1][qr] = v.y * 0.125f;
        Qs[d4+2][qr] = v.z * 0.125f; Qs[d4+3][qr] = v.w * 0.125f;
    }

    float m[4], l[4], o[4][4];
    #pragma unroll
    for (int i = 0; i < 4; i++) {
        m[i] = -1e30f; l[i] = 0.f;
        #pragma unroll
        for (int j = 0; j < 4; j++) o[i][j] = 0.f;
    }

    for (int kb = 0; kb <= qb; kb++) {
        __syncthreads();   // previous iteration's reads of KP/Vs are done
        for (int i = tid; i < 64 * 16; i += 256) {
            int kc = i >> 4, d4 = (i & 15) * 4;
            long long rowoff = (long long)(kb * 64 + kc) * (3 * HDIM) + h * DHEAD + d4;
            float4 kv = *(const float4*)&base[rowoff + HDIM];
            KP[d4+0][kc] = kv.x; KP[d4+1][kc] = kv.y; KP[d4+2][kc] = kv.z; KP[d4+3][kc] = kv.w;
            float4 vv = *(const float4*)&base[rowoff + 2 * HDIM];
            *(float4*)&Vs[kc][d4] = vv;
        }
        __syncthreads();

        // S = Q K^T
        float s[4][4];
        #pragma unroll
        for (int i = 0; i < 4; i++)
            #pragma unroll
            for (int j = 0; j < 4; j++) s[i][j] = 0.f;
        #pragma unroll 16
        for (int kk = 0; kk < 64; kk++) {
            float4 aq = *(const float4*)&Qs[kk][ty * 4];
            float4 bk = *(const float4*)&KP[kk][tx * 4];
            float ar[4] = {aq.x, aq.y, aq.z, aq.w};
            float br[4] = {bk.x, bk.y, bk.z, bk.w};
            #pragma unroll
            for (int i = 0; i < 4; i++)
                #pragma unroll
                for (int j = 0; j < 4; j++)
                    s[i][j] += ar[i] * br[j];
        }

        // causal mask on diagonal tile
        if (kb == qb) {
            #pragma unroll
            for (int i = 0; i < 4; i++) {
                int qg = ty * 4 + i;
                #pragma unroll
                for (int j = 0; j < 4; j++)
                    if (tx * 4 + j > qg) s[i][j] = -1e9f;
            }
        }

        // online softmax: per-row stats shared by the 16 tx-lanes of each ty group
        #pragma unroll
        for (int i = 0; i < 4; i++) {
            float rm = fmaxf(fmaxf(s[i][0], s[i][1]), fmaxf(s[i][2], s[i][3]));
            #pragma unroll
            for (int off = 1; off < 16; off <<= 1)
                rm = fmaxf(rm, __shfl_xor_sync(0xffffffffu, rm, off, 16));
            float mnew = fmaxf(m[i], rm);
            float scale = __expf(m[i] - mnew);
            m[i] = mnew;
            float rsum = 0.f;
            #pragma unroll
            for (int j = 0; j < 4; j++) {
                float p = __expf(s[i][j] - mnew);
                s[i][j] = p; rsum += p;
            }
            #pragma unroll
            for (int off = 1; off < 16; off <<= 1)
                rsum += __shfl_xor_sync(0xffffffffu, rsum, off, 16);
            l[i] = l[i] * scale + rsum;
            #pragma unroll
            for (int j = 0; j < 4; j++) o[i][j] *= scale;
        }

        __syncthreads();   // everyone finished reading KP (K data)
        #pragma unroll
        for (int i = 0; i < 4; i++)
            #pragma unroll
            for (int j = 0; j < 4; j++)
                KP[tx * 4 + j][ty * 4 + i] = s[i][j];
        __syncthreads();

        // O += P V
        #pragma unroll 16
        for (int kk = 0; kk < 64; kk++) {
            float4 ap = *(const float4*)&KP[kk][ty * 4];
            float4 bv = *(const float4*)&Vs[kk][tx * 4];
            float ar[4] = {ap.x, ap.y, ap.z, ap.w};
            float br[4] = {bv.x, bv.y, bv.z, bv.w};
            #pragma unroll
            for (int i = 0; i < 4; i++)
                #pragma unroll
                for (int j = 0; j < 4; j++)
                    o[i][j] += ar[i] * br[j];
        }
    }

    #pragma unroll
    for (int i = 0; i < 4; i++) {
        float inv = 1.0f / l[i];
        long long t = (long long)b * S_LEN + qb * 64 + ty * 4 + i;
        #pragma unroll
        for (int j = 0; j < 4; j++)
            ctx[t * HDIM + h * DHEAD + tx * 4 + j] = o[i][j] * inv;
    }
}

// ---------------- router: GEMV(16x256) + softmax + top-4 + renorm ------------
__global__ __launch_bounds__(128) void router_kernel(
    const float* __restrict__ r1, const float* __restrict__ Wr2,
    const float* __restrict__ br2, float* __restrict__ wout)
{
    int t = blockIdx.x;
    int tid = threadIdx.x;
    int p = tid >> 3, lane8 = tid & 7;

    const float4* a4 = (const float4*)(r1 + (long long)t * 256);
    const float4* w4 = (const float4*)(Wr2 + (long long)p * 256);
    float s = 0.f;
    #pragma unroll
    for (int j = 0; j < 8; j++) {
        float4 av = a4[lane8 * 8 + j];
        float4 wv = w4[lane8 * 8 + j];
        s += av.x * wv.x + av.y * wv.y + av.z * wv.z + av.w * wv.w;
    }
    #pragma unroll
    for (int o = 1; o < 8; o <<= 1) s += __shfl_xor_sync(0xffffffffu, s, o, 8);

    __shared__ float rv[16];
    if (lane8 == 0) rv[p] = s + br2[p];
    __syncthreads();

    if (tid == 0) {
        float pr[16];
        float vmax = rv[0];
        #pragma unroll
        for (int i = 1; i < 16; i++) vmax = fmaxf(vmax, rv[i]);
        float sum = 0.f;
        #pragma unroll
        for (int i = 0; i < 16; i++) { pr[i] = __expf(rv[i] - vmax); sum += pr[i]; }
        float inv = 1.0f / sum;
        #pragma unroll
        for (int i = 0; i < 16; i++) pr[i] *= inv;

        bool sel[16];
        #pragma unroll
        for (int i = 0; i < 16; i++) sel[i] = false;
        float ssum = 0.f;
        for (int k = 0; k < 4; k++) {
            int best = 0; float bv = -1.0f;
            for (int i = 0; i < 16; i++)
                if (!sel[i] && pr[i] > bv) { bv = pr[i]; best = i; }
            sel[best] = true; ssum += bv;
        }
        float dinv = 1.0f / (ssum + 1e-8f);
        for (int i = 0; i < 16; i++)
            wout[(long long)t * 16 + i] = sel[i] ? pr[i] * dinv : 0.f;
    }
}

// ---------------- launch ----------------
extern "C" void kernel_launch(void* const* d_in, const int* in_sizes, int n_in,
                              void* d_out, int out_size)
{
    const float* hidden = (const float*)d_in[0];
    const float* ln1w   = (const float*)d_in[1];
    const float* ln1b   = (const float*)d_in[2];
    const float* Wqkv   = (const float*)d_in[3];
    const float* bqkv   = (const float*)d_in[4];
    const float* Wo     = (const float*)d_in[5];
    const float* bo     = (const float*)d_in[6];
    const float* ln2w   = (const float*)d_in[7];
    const float* ln2b   = (const float*)d_in[8];
    const float* Wr1    = (const float*)d_in[9];
    const float* br1    = (const float*)d_in[10];
    const float* Wr2    = (const float*)d_in[11];
    const float* br2    = (const float*)d_in[12];
    const float* W1     = (const float*)d_in[13];
    const float* b1     = (const float*)d_in[14];
    const float* W2     = (const float*)d_in[15];
    const float* b2     = (const float*)d_in[16];
    float* out = (float*)d_out;

    float *x, *qkv, *ctx, *h, *x2, *r1, *wv, *inter;
    cudaGetSymbolAddress((void**)&x,     g_x_);
    cudaGetSymbolAddress((void**)&qkv,   g_qkv_);
    cudaGetSymbolAddress((void**)&ctx,   g_ctx_);
    cudaGetSymbolAddress((void**)&h,     g_h_);
    cudaGetSymbolAddress((void**)&x2,    g_x2_);
    cudaGetSymbolAddress((void**)&r1,    g_r1_);
    cudaGetSymbolAddress((void**)&wv,    g_w_);
    cudaGetSymbolAddress((void**)&inter, g_int_);

    // 1) LN1
    ln_kernel<<<NTOK, 256>>>(hidden, ln1w, ln1b, x);
    // 2) QKV = x @ Wqkv^T + bqkv            [4096 x 3072]
    tgemm_kernel<0><<<dim3(3072/64, NTOK/128, 1), 256>>>(
        x, HDIM, 0, Wqkv, HDIM, 0, qkv, 3*HDIM, 0, HDIM,
        bqkv, 0, nullptr, 0, 0, nullptr);
    // 3) causal attention -> ctx
    attn_kernel<<<dim3(S_LEN/64, NHEADS, 4), 256>>>(qkv, ctx);
    // 4) h = hidden + ctx @ Wo^T + bo
    tgemm_kernel<1><<<dim3(HDIM/64, NTOK/128, 1), 256>>>(
        ctx, HDIM, 0, Wo, HDIM, 0, h, HDIM, 0, HDIM,
        bo, 0, hidden, 0, HDIM, nullptr);
    // 5) LN2
    ln_kernel<<<NTOK, 256>>>(h, ln2w, ln2b, x2);
    // 6) r1 = relu(x2 @ Wr1^T + br1)        [4096 x 256]
    tgemm_kernel<2><<<dim3(256/64, NTOK/128, 1), 256>>>(
        x2, HDIM, 0, Wr1, HDIM, 0, r1, 256, 0, HDIM,
        br1, 0, nullptr, 0, 0, nullptr);
    // 7) router logits + softmax + top-4 + renorm -> w [4096 x 16]
    router_kernel<<<NTOK, 128>>>(r1, Wr2, br2, wv);
    // 8) inter_p = gelu(x2_p @ W1b_p^T + b1_p)   (z = pathway)
    tgemm_kernel<3><<<dim3(256/64, NTOK/128, PATHS), 256>>>(
        x2, HDIM, 64, W1, HDIM, (long long)256*HDIM + 64,
        inter, 256, (long long)NTOK*256, 64,
        b1, 256, nullptr, 0, 0, nullptr);
    // 9) out = h + (inter_p @ W2b_p^T + b2_p) * w[:,p]   (z = pathway)
    tgemm_kernel<4><<<dim3(1, NTOK/128, PATHS), 256>>>(
        inter, 256, (long long)NTOK*256, W2, 4096, (long long)64*4096 + 256,
        out, HDIM, 64, 256,
        b2, 64, h, 64, HDIM, wv);
}

// round 14
// speedup vs baseline: 1.3512x; 1.3205x over previous
#include <cuda_runtime.h>
#include <cuda_fp16.h>
#include <math.h>
#include <stdint.h>

#define S_LEN  1024
#define HDIM   1024
#define NTOK   4096            // B*S
#define NHEADS 16
#define DHEAD  64
#define PATHS  16

// ---------------- scratch (static __device__, no allocation) ----------------
__device__ float4 g_x_   [NTOK*HDIM/4];        // ln1 out
__device__ float4 g_qkv_ [NTOK*3*HDIM/4];      // qkv
__device__ float4 g_ctx_ [NTOK*HDIM/4];        // attention context
__device__ float4 g_h_   [NTOK*HDIM/4];        // residual-1 out
__device__ float4 g_x2_  [NTOK*HDIM/4];        // ln2 out
__device__ float4 g_r1_  [NTOK*256/4];         // router hidden
__device__ float4 g_w_   [NTOK*PATHS/4];       // pathway weights
__device__ float4 g_int_ [(long long)PATHS*NTOK*256/4]; // pathway intermediates

// ---------------- LayerNorm (one block per row of 1024) ----------------
__global__ __launch_bounds__(256) void ln_kernel(
    const float* __restrict__ x, const float* __restrict__ gamma,
    const float* __restrict__ beta, float* __restrict__ y)
{
    long long row = blockIdx.x;
    const float* xr = x + row * HDIM;
    float* yr = y + row * HDIM;
    int tid = threadIdx.x;

    float4 v = *(const float4*)&xr[tid * 4];
    float s  = v.x + v.y + v.z + v.w;
    float ss = v.x*v.x + v.y*v.y + v.z*v.z + v.w*v.w;
    #pragma unroll
    for (int o = 16; o; o >>= 1) {
        s  += __shfl_xor_sync(0xffffffffu, s,  o);
        ss += __shfl_xor_sync(0xffffffffu, ss, o);
    }
    __shared__ float rs[8], rss[8];
    int w = tid >> 5, ln = tid & 31;
    if (ln == 0) { rs[w] = s; rss[w] = ss; }
    __syncthreads();
    s = 0.f; ss = 0.f;
    #pragma unroll
    for (int i = 0; i < 8; i++) { s += rs[i]; ss += rss[i]; }

    float mean = s * (1.0f / HDIM);
    float var  = ss * (1.0f / HDIM) - mean * mean;
    float inv  = rsqrtf(var + 1e-5f);

    float4 g = *(const float4*)&gamma[tid * 4];
    float4 b = *(const float4*)&beta[tid * 4];
    float4 o;
    o.x = (v.x - mean) * inv * g.x + b.x;
    o.y = (v.y - mean) * inv * g.y + b.y;
    o.z = (v.z - mean) * inv * g.z + b.z;
    o.w = (v.w - mean) * inv * g.w + b.w;
    *(float4*)&yr[tid * 4] = o;
}

// ---------------- fp16 tensor-core GEMM: C[M,N] = A[M,K] @ B[N,K]^T ---------
// BM=128, BN=64, BK=32, 256 threads (8 warps), warp tile 32x32 via
// mma.sync.m16n8k16.row.col.f32.f16.f16.f32 (fp32 accumulate).
// Smem rows padded to 40 halves so fragment loads are bank-conflict-free
// (bank = (20*row + t) mod 32, all distinct across a warp).
// EPI: 0=bias  1=bias+res  2=bias+relu  3=gelu(bias)  4=res + (acc+bias)*w[row,z]
__device__ __forceinline__ float gelu_tanh(float x) {
    float t = tanhf(0.7978845608028654f * (x + 0.044715f * x * x * x));
    return 0.5f * x * (1.0f + t);
}

__device__ __forceinline__ void mma_f16(float c[4], const uint32_t a[4], const uint32_t b[2]) {
    asm volatile(
        "mma.sync.aligned.m16n8k16.row.col.f32.f16.f16.f32 "
        "{%0,%1,%2,%3}, {%4,%5,%6,%7}, {%8,%9}, {%0,%1,%2,%3};\n"
        : "+f"(c[0]), "+f"(c[1]), "+f"(c[2]), "+f"(c[3])
        : "r"(a[0]), "r"(a[1]), "r"(a[2]), "r"(a[3]), "r"(b[0]), "r"(b[1]));
}

template<int EPI>
__global__ __launch_bounds__(256) void tgemm_kernel(
    const float* __restrict__ A, int lda, long long aZ,
    const float* __restrict__ B, int ldb, long long bZ,
    float* __restrict__ C, int ldc, long long cZ,
    int K,
    const float* __restrict__ bias, int biasZ,
    const float* __restrict__ res, long long resZ, int ldres,
    const float* __restrict__ wvec)
{
    const int z = blockIdx.z;
    A += (long long)z * aZ;
    B += (long long)z * bZ;
    C += (long long)z * cZ;
    bias += (long long)z * biasZ;
    if (EPI == 1 || EPI == 4) res += (long long)z * resZ;

    __shared__ __align__(16) __half As[128][40];   // 128 x 32 data, stride 40
    __shared__ __align__(16) __half Bs[64][40];

    const int tid  = threadIdx.x;
    const int warp = tid >> 5;
    const int lane = tid & 31;
    const int g = lane >> 2;           // groupID
    const int t = lane & 3;            // threadID_in_group
    const int wm = (warp & 3) * 32;    // warp m-offset
    const int wn = (warp >> 2) * 32;   // warp n-offset
    const int bm = blockIdx.y * 128, bn = blockIdx.x * 64;

    float acc[2][4][4];
    #pragma unroll
    for (int i = 0; i < 2; i++)
        #pragma unroll
        for (int j = 0; j < 4; j++)
            #pragma unroll
            for (int q = 0; q < 4; q++) acc[i][j][q] = 0.f;

    for (int k0 = 0; k0 < K; k0 += 32) {
        // global loads (fp32): A 4 chunks/thread, B 2 chunks/thread
        float4 av[4], bv[2];
        #pragma unroll
        for (int i = 0; i < 4; i++) {
            const int c = tid + i * 256, row = c >> 3, kc = c & 7;
            av[i] = *(const float4*)&A[(long long)(bm + row) * lda + k0 + kc * 4];
        }
        #pragma unroll
        for (int i = 0; i < 2; i++) {
            const int c = tid + i * 256, row = c >> 3, kc = c & 7;
            bv[i] = *(const float4*)&B[(long long)(bn + row) * ldb + k0 + kc * 4];
        }
        if (k0) __syncthreads();
        #pragma unroll
        for (int i = 0; i < 4; i++) {
            const int c = tid + i * 256, row = c >> 3, kc = c & 7;
            *(half2*)&As[row][kc * 4]     = __floats2half2_rn(av[i].x, av[i].y);
            *(half2*)&As[row][kc * 4 + 2] = __floats2half2_rn(av[i].z, av[i].w);
        }
        #pragma unroll
        for (int i = 0; i < 2; i++) {
            const int c = tid + i * 256, row = c >> 3, kc = c & 7;
            *(half2*)&Bs[row][kc * 4]     = __floats2half2_rn(bv[i].x, bv[i].y);
            *(half2*)&Bs[row][kc * 4 + 2] = __floats2half2_rn(bv[i].z, bv[i].w);
        }
        __syncthreads();

        #pragma unroll
        for (int ks = 0; ks < 32; ks += 16) {
            uint32_t af[2][4], bf[4][2];
            #pragma unroll
            for (int i = 0; i < 2; i++) {
                const int r0 = wm + 16 * i + g;
                af[i][0] = *(const uint32_t*)&As[r0    ][ks + 2 * t];
                af[i][1] = *(const uint32_t*)&As[r0 + 8][ks + 2 * t];
                af[i][2] = *(const uint32_t*)&As[r0    ][ks + 2 * t + 8];
                af[i][3] = *(const uint32_t*)&As[r0 + 8][ks + 2 * t + 8];
            }
            #pragma unroll
            for (int j = 0; j < 4; j++) {
                const int cn = wn + 8 * j + g;
                bf[j][0] = *(const uint32_t*)&Bs[cn][ks + 2 * t];
                bf[j][1] = *(const uint32_t*)&Bs[cn][ks + 2 * t + 8];
            }
            #pragma unroll
            for (int i = 0; i < 2; i++)
                #pragma unroll
                for (int j = 0; j < 4; j++)
                    mma_f16(acc[i][j], af[i], bf[j]);
        }
    }

    // epilogue: thread holds rows (bm+wm+16i+g) and (+8), cols (bn+wn+8j+2t, +1)
    #pragma unroll
    for (int i = 0; i < 2; i++) {
        const long long r0 = bm + wm + 16*i + g;
        const long long r1 = r0 + 8;
        float w0 = 0.f, w1 = 0.f;
        if (EPI == 4) { w0 = wvec[r0 * PATHS + z]; w1 = wvec[r1 * PATHS + z]; }
        #pragma unroll
        for (int j = 0; j < 4; j++) {
            const int col = bn + wn + 8*j + 2*t;
            const float bx = bias[col], by = bias[col + 1];
            float v0 = acc[i][j][0] + bx, v1 = acc[i][j][1] + by;   // row r0
            float v2 = acc[i][j][2] + bx, v3 = acc[i][j][3] + by;   // row r1
            if (EPI == 1) {
                float2 q0 = *(const float2*)&res[r0 * ldres + col];
                float2 q1 = *(const float2*)&res[r1 * ldres + col];
                v0 += q0.x; v1 += q0.y; v2 += q1.x; v3 += q1.y;
            }
            if (EPI == 2) { v0 = fmaxf(v0,0.f); v1 = fmaxf(v1,0.f); v2 = fmaxf(v2,0.f); v3 = fmaxf(v3,0.f); }
            if (EPI == 3) { v0 = gelu_tanh(v0); v1 = gelu_tanh(v1); v2 = gelu_tanh(v2); v3 = gelu_tanh(v3); }
            if (EPI == 4) {
                float2 q0 = *(const float2*)&res[r0 * ldres + col];
                float2 q1 = *(const float2*)&res[r1 * ldres + col];
                v0 = q0.x + v0 * w0; v1 = q0.y + v1 * w0;
                v2 = q1.x + v2 * w1; v3 = q1.y + v3 * w1;
            }
            *(float2*)&C[r0 * ldc + col] = make_float2(v0, v1);
            *(float2*)&C[r1 * ldc + col] = make_float2(v2, v3);
        }
    }
}

// ---------------- flash attention: 64 q-rows per block, Dh=64 ----------------
__global__ __launch_bounds__(256) void attn_kernel(
    const float* __restrict__ qkv, float* __restrict__ ctx)
{
    const int qb = blockIdx.x;     // 0..15 (q tile)
    const int h  = blockIdx.y;     // head
    const int b  = blockIdx.z;     // batch
    const float* base = qkv + (long long)b * S_LEN * 3 * HDIM;

    __shared__ __align__(16) float Qs[64][64];   // [d][qr], pre-scaled
    __shared__ __align__(16) float KP[64][64];   // K as [d][kc], then P as [kc][qr]
    __shared__ __align__(16) float Vs[64][64];   // [kv][d]

    const int tid = threadIdx.x;
    const int tx = tid & 15, ty = tid >> 4;

    for (int i = tid; i < 64 * 16; i += 256) {
        int qr = i >> 4, d4 = (i & 15) * 4;
        float4 v = *(const float4*)&base[(long long)(qb * 64 + qr) * (3 * HDIM) + h * DHEAD + d4];
        Qs[d4+0][qr] = v.x * 0.125f; Qs[d4+1][qr] = v.y * 0.125f;
        Qs[d4+2][qr] = v.z * 0.125f; Qs[d4+3][qr] = v.w * 0.125f;
    }

    float m[4], l[4], o[4][4];
    #pragma unroll
    for (int i = 0; i < 4; i++) {
        m[i] = -1e30f; l[i] = 0.f;
        #pragma unroll
        for (int j = 0; j < 4; j++) o[i][j] = 0.f;
    }

    for (int kb = 0; kb <= qb; kb++) {
        __syncthreads();
        for (int i = tid; i < 64 * 16; i += 256) {
            int kc = i >> 4, d4 = (i & 15) * 4;
            long long rowoff = (long long)(kb * 64 + kc) * (3 * HDIM) + h * DHEAD + d4;
            float4 kv = *(const float4*)&base[rowoff + HDIM];
            KP[d4+0][kc] = kv.x; KP[d4+1][kc] = kv.y; KP[d4+2][kc] = kv.z; KP[d4+3][kc] = kv.w;
            float4 vv = *(const float4*)&base[rowoff + 2 * HDIM];
            *(float4*)&Vs[kc][d4] = vv;
        }
        __syncthreads();

        float s[4][4];
        #pragma unroll
        for (int i = 0; i < 4; i++)
            #pragma unroll
            for (int j = 0; j < 4; j++) s[i][j] = 0.f;
        #pragma unroll 16
        for (int kk = 0; kk < 64; kk++) {
            float4 aq = *(const float4*)&Qs[kk][ty * 4];
            float4 bk = *(const float4*)&KP[kk][tx * 4];
            float ar[4] = {aq.x, aq.y, aq.z, aq.w};
            float br[4] = {bk.x, bk.y, bk.z, bk.w};
            #pragma unroll
            for (int i = 0; i < 4; i++)
                #pragma unroll
                for (int j = 0; j < 4; j++)
                    s[i][j] += ar[i] * br[j];
        }

        if (kb == qb) {
            #pragma unroll
            for (int i = 0; i < 4; i++) {
                int qg = ty * 4 + i;
                #pragma unroll
                for (int j = 0; j < 4; j++)
                    if (tx * 4 + j > qg) s[i][j] = -1e9f;
            }
        }

        #pragma unroll
        for (int i = 0; i < 4; i++) {
            float rm = fmaxf(fmaxf(s[i][0], s[i][1]), fmaxf(s[i][2], s[i][3]));
            #pragma unroll
            for (int off = 1; off < 16; off <<= 1)
                rm = fmaxf(rm, __shfl_xor_sync(0xffffffffu, rm, off, 16));
            float mnew = fmaxf(m[i], rm);
            float scale = __expf(m[i] - mnew);
            m[i] = mnew;
            float rsum = 0.f;
            #pragma unroll
            for (int j = 0; j < 4; j++) {
                float p = __expf(s[i][j] - mnew);
                s[i][j] = p; rsum += p;
            }
            #pragma unroll
            for (int off = 1; off < 16; off <<= 1)
                rsum += __shfl_xor_sync(0xffffffffu, rsum, off, 16);
            l[i] = l[i] * scale + rsum;
            #pragma unroll
            for (int j = 0; j < 4; j++) o[i][j] *= scale;
        }

        __syncthreads();
        #pragma unroll
        for (int i = 0; i < 4; i++)
            #pragma unroll
            for (int j = 0; j < 4; j++)
                KP[tx * 4 + j][ty * 4 + i] = s[i][j];
        __syncthreads();

        #pragma unroll 16
        for (int kk = 0; kk < 64; kk++) {
            float4 ap = *(const float4*)&KP[kk][ty * 4];
            float4 bv = *(const float4*)&Vs[kk][tx * 4];
            float ar[4] = {ap.x, ap.y, ap.z, ap.w};
            float br[4] = {bv.x, bv.y, bv.z, bv.w};
            #pragma unroll
            for (int i = 0; i < 4; i++)
                #pragma unroll
                for (int j = 0; j < 4; j++)
                    o[i][j] += ar[i] * br[j];
        }
    }

    #pragma unroll
    for (int i = 0; i < 4; i++) {
        float inv = 1.0f / l[i];
        long long t = (long long)b * S_LEN + qb * 64 + ty * 4 + i;
        #pragma unroll
        for (int j = 0; j < 4; j++)
            ctx[t * HDIM + h * DHEAD + tx * 4 + j] = o[i][j] * inv;
    }
}

// ---------------- router: GEMV(16x256) + softmax + top-4 + renorm ------------
__global__ __launch_bounds__(128) void router_kernel(
    const float* __restrict__ r1, const float* __restrict__ Wr2,
    const float* __restrict__ br2, float* __restrict__ wout)
{
    int t = blockIdx.x;
    int tid = threadIdx.x;
    int p = tid >> 3, lane8 = tid & 7;

    const float4* a4 = (const float4*)(r1 + (long long)t * 256);
    const float4* w4 = (const float4*)(Wr2 + (long long)p * 256);
    float s = 0.f;
    #pragma unroll
    for (int j = 0; j < 8; j++) {
        float4 av = a4[lane8 * 8 + j];
        float4 wv = w4[lane8 * 8 + j];
        s += av.x * wv.x + av.y * wv.y + av.z * wv.z + av.w * wv.w;
    }
    #pragma unroll
    for (int o = 1; o < 8; o <<= 1) s += __shfl_xor_sync(0xffffffffu, s, o, 8);

    __shared__ float rv[16];
    if (lane8 == 0) rv[p] = s + br2[p];
    __syncthreads();

    if (tid == 0) {
        float pr[16];
        float vmax = rv[0];
        #pragma unroll
        for (int i = 1; i < 16; i++) vmax = fmaxf(vmax, rv[i]);
        float sum = 0.f;
        #pragma unroll
        for (int i = 0; i < 16; i++) { pr[i] = __expf(rv[i] - vmax); sum += pr[i]; }
        float inv = 1.0f / sum;
        #pragma unroll
        for (int i = 0; i < 16; i++) pr[i] *= inv;

        bool sel[16];
        #pragma unroll
        for (int i = 0; i < 16; i++) sel[i] = false;
        float ssum = 0.f;
        for (int k = 0; k < 4; k++) {
            int best = 0; float bv = -1.0f;
            for (int i = 0; i < 16; i++)
                if (!sel[i] && pr[i] > bv) { bv = pr[i]; best = i; }
            sel[best] = true; ssum += bv;
        }
        float dinv = 1.0f / (ssum + 1e-8f);
        for (int i = 0; i < 16; i++)
            wout[(long long)t * 16 + i] = sel[i] ? pr[i] * dinv : 0.f;
    }
}

// ---------------- launch ----------------
extern "C" void kernel_launch(void* const* d_in, const int* in_sizes, int n_in,
                              void* d_out, int out_size)
{
    const float* hidden = (const float*)d_in[0];
    const float* ln1w   = (const float*)d_in[1];
    const float* ln1b   = (const float*)d_in[2];
    const float* Wqkv   = (const float*)d_in[3];
    const float* bqkv   = (const float*)d_in[4];
    const float* Wo     = (const float*)d_in[5];
    const float* bo     = (const float*)d_in[6];
    const float* ln2w   = (const float*)d_in[7];
    const float* ln2b   = (const float*)d_in[8];
    const float* Wr1    = (const float*)d_in[9];
    const float* br1    = (const float*)d_in[10];
    const float* Wr2    = (const float*)d_in[11];
    const float* br2    = (const float*)d_in[12];
    const float* W1     = (const float*)d_in[13];
    const float* b1     = (const float*)d_in[14];
    const float* W2     = (const float*)d_in[15];
    const float* b2     = (const float*)d_in[16];
    float* out = (float*)d_out;

    float *x, *qkv, *ctx, *h, *x2, *r1, *wv, *inter;
    cudaGetSymbolAddress((void**)&x,     g_x_);
    cudaGetSymbolAddress((void**)&qkv,   g_qkv_);
    cudaGetSymbolAddress((void**)&ctx,   g_ctx_);
    cudaGetSymbolAddress((void**)&h,     g_h_);
    cudaGetSymbolAddress((void**)&x2,    g_x2_);
    cudaGetSymbolAddress((void**)&r1,    g_r1_);
    cudaGetSymbolAddress((void**)&wv,    g_w_);
    cudaGetSymbolAddress((void**)&inter, g_int_);

    // 1) LN1
    ln_kernel<<<NTOK, 256>>>(hidden, ln1w, ln1b, x);
    // 2) QKV = x @ Wqkv^T + bqkv            [4096 x 3072]
    tgemm_kernel<0><<<dim3(3072/64, NTOK/128, 1), 256>>>(
        x, HDIM, 0, Wqkv, HDIM, 0, qkv, 3*HDIM, 0, HDIM,
        bqkv, 0, nullptr, 0, 0, nullptr);
    // 3) causal attention -> ctx
    attn_kernel<<<dim3(S_LEN/64, NHEADS, 4), 256>>>(qkv, ctx);
    // 4) h = hidden + ctx @ Wo^T + bo
    tgemm_kernel<1><<<dim3(HDIM/64, NTOK/128, 1), 256>>>(
        ctx, HDIM, 0, Wo, HDIM, 0, h, HDIM, 0, HDIM,
        bo, 0, hidden, 0, HDIM, nullptr);
    // 5) LN2
    ln_kernel<<<NTOK, 256>>>(h, ln2w, ln2b, x2);
    // 6) r1 = relu(x2 @ Wr1^T + br1)        [4096 x 256]
    tgemm_kernel<2><<<dim3(256/64, NTOK/128, 1), 256>>>(
        x2, HDIM, 0, Wr1, HDIM, 0, r1, 256, 0, HDIM,
        br1, 0, nullptr, 0, 0, nullptr);
    // 7) router logits + softmax + top-4 + renorm -> w [4096 x 16]
    router_kernel<<<NTOK, 128>>>(r1, Wr2, br2, wv);
    // 8) inter_p = gelu(x2_p @ W1b_p^T + b1_p)   (z = pathway)
    tgemm_kernel<3><<<dim3(256/64, NTOK/128, PATHS), 256>>>(
        x2, HDIM, 64, W1, HDIM, (long long)256*HDIM + 64,
        inter, 256, (long long)NTOK*256, 64,
        b1, 256, nullptr, 0, 0, nullptr);
    // 9) out = h + (inter_p @ W2b_p^T + b2_p) * w[:,p]   (z = pathway)
    tgemm_kernel<4><<<dim3(1, NTOK/128, PATHS), 256>>>(
        inter, 256, (long long)NTOK*256, W2, 4096, (long long)64*4096 + 256,
        out, HDIM, 64, 256,
        b2, 64, h, 64, HDIM, wv);
}

// round 15
// speedup vs baseline: 1.5053x; 1.1141x over previous
#include <cuda_runtime.h>
#include <cuda_fp16.h>
#include <math.h>
#include <stdint.h>

#define S_LEN  1024
#define HDIM   1024
#define NTOK   4096            // B*S
#define NHEADS 16
#define DHEAD  64
#define PATHS  16

// ---------------- scratch (static __device__, no allocation) ----------------
__device__ float4 g_qkv_ [NTOK*3*HDIM/4];      // qkv (fp32, attention input)
__device__ float4 g_h_   [NTOK*HDIM/4];        // residual-1 out (fp32)
__device__ float4 g_r1_  [NTOK*256/4];         // router hidden (fp32)
__device__ float4 g_w_   [NTOK*PATHS/4];       // pathway weights (fp32)
__device__ __half g_xh_   [NTOK*HDIM];         // ln1 out (half)
__device__ __half g_ctxh_ [NTOK*HDIM];         // attention context (half)
__device__ __half g_x2h_  [NTOK*HDIM];         // ln2 out (half)
__device__ __half g_inth_ [(long long)PATHS*NTOK*256]; // pathway intermediates (half)
__device__ __half g_wqkvh_[3*HDIM*HDIM];
__device__ __half g_woh_  [HDIM*HDIM];
__device__ __half g_wr1h_ [256*HDIM];
__device__ __half g_w1h_  [4096*HDIM];
__device__ __half g_w2h_  [HDIM*4096];

// ---------------- fp32 -> fp16 convert ----------------
__global__ __launch_bounds__(256) void f2h_kernel(
    const float* __restrict__ s, __half* __restrict__ d, int n)
{
    int i = (blockIdx.x * 256 + threadIdx.x) * 4;
    if (i < n) {
        float4 v = *(const float4*)&s[i];
        *(half2*)&d[i]     = __floats2half2_rn(v.x, v.y);
        *(half2*)&d[i + 2] = __floats2half2_rn(v.z, v.w);
    }
}

// ---------------- LayerNorm (fp32 in, fp16 out) ----------------
__global__ __launch_bounds__(256) void ln_kernel(
    const float* __restrict__ x, const float* __restrict__ gamma,
    const float* __restrict__ beta, __half* __restrict__ y)
{
    long long row = blockIdx.x;
    const float* xr = x + row * HDIM;
    __half* yr = y + row * HDIM;
    int tid = threadIdx.x;

    float4 v = *(const float4*)&xr[tid * 4];
    float s  = v.x + v.y + v.z + v.w;
    float ss = v.x*v.x + v.y*v.y + v.z*v.z + v.w*v.w;
    #pragma unroll
    for (int o = 16; o; o >>= 1) {
        s  += __shfl_xor_sync(0xffffffffu, s,  o);
        ss += __shfl_xor_sync(0xffffffffu, ss, o);
    }
    __shared__ float rs[8], rss[8];
    int w = tid >> 5, ln = tid & 31;
    if (ln == 0) { rs[w] = s; rss[w] = ss; }
    __syncthreads();
    s = 0.f; ss = 0.f;
    #pragma unroll
    for (int i = 0; i < 8; i++) { s += rs[i]; ss += rss[i]; }

    float mean = s * (1.0f / HDIM);
    float var  = ss * (1.0f / HDIM) - mean * mean;
    float inv  = rsqrtf(var + 1e-5f);

    float4 g = *(const float4*)&gamma[tid * 4];
    float4 b = *(const float4*)&beta[tid * 4];
    float o0 = (v.x - mean) * inv * g.x + b.x;
    float o1 = (v.y - mean) * inv * g.y + b.y;
    float o2 = (v.z - mean) * inv * g.z + b.z;
    float o3 = (v.w - mean) * inv * g.w + b.w;
    *(half2*)&yr[tid * 4]     = __floats2half2_rn(o0, o1);
    *(half2*)&yr[tid * 4 + 2] = __floats2half2_rn(o2, o3);
}

// ---------------- fp16 tensor-core GEMM: C = A[M,K] @ B[N,K]^T --------------
// BM=128, BN in {64,128}, BK=32, 256 threads (8 warps).
// Warp grid 4(M) x 2(N); warp tile 32 x (BN/2). mma.m16n8k16 f32.f16.f16.f32.
// A,B are __half. C type CT (float or __half).
// EPI: 0=bias  1=bias+res  2=bias+relu  3=gelu(bias)  4=res + (acc+bias)*w[row,z]
__device__ __forceinline__ float gelu_tanh(float x) {
    float t = tanhf(0.7978845608028654f * (x + 0.044715f * x * x * x));
    return 0.5f * x * (1.0f + t);
}

__device__ __forceinline__ void mma_f16(float c[4], const uint32_t a[4], const uint32_t b[2]) {
    asm volatile(
        "mma.sync.aligned.m16n8k16.row.col.f32.f16.f16.f32 "
        "{%0,%1,%2,%3}, {%4,%5,%6,%7}, {%8,%9}, {%0,%1,%2,%3};\n"
        : "+f"(c[0]), "+f"(c[1]), "+f"(c[2]), "+f"(c[3])
        : "r"(a[0]), "r"(a[1]), "r"(a[2]), "r"(a[3]), "r"(b[0]), "r"(b[1]));
}

template<int EPI, int BN, typename CT>
__global__ __launch_bounds__(256) void tgemm_kernel(
    const __half* __restrict__ A, int lda, long long aZ,
    const __half* __restrict__ B, int ldb, long long bZ,
    CT* __restrict__ C, int ldc, long long cZ,
    int K,
    const float* __restrict__ bias, int biasZ,
    const float* __restrict__ res, long long resZ, int ldres,
    const float* __restrict__ wvec)
{
    const int z = blockIdx.z;
    A += (long long)z * aZ;
    B += (long long)z * bZ;
    C += (long long)z * cZ;
    bias += (long long)z * biasZ;
    if (EPI == 1 || EPI == 4) res += (long long)z * resZ;

    __shared__ __align__(16) __half As[128][40];   // 128 x 32 data, stride 40
    __shared__ __align__(16) __half Bs[BN][40];

    const int tid  = threadIdx.x;
    const int warp = tid >> 5;
    const int lane = tid & 31;
    const int g = lane >> 2;               // groupID
    const int t = lane & 3;                // threadID_in_group
    const int wm = (warp & 3) * 32;        // warp m-offset
    const int wn = (warp >> 2) * (BN / 2); // warp n-offset
    const int bm = blockIdx.y * 128, bn = blockIdx.x * BN;
    const int NF = BN / 16;                // n-fragments per warp

    float acc[2][BN/16][4];
    #pragma unroll
    for (int i = 0; i < 2; i++)
        #pragma unroll
        for (int j = 0; j < NF; j++)
            #pragma unroll
            for (int q = 0; q < 4; q++) acc[i][j][q] = 0.f;

    for (int k0 = 0; k0 < K; k0 += 32) {
        uint4 av[2], bv[BN/64];
        #pragma unroll
        for (int i = 0; i < 2; i++) {
            const int c = tid + i * 256, row = c >> 2, kc = c & 3;
            av[i] = *(const uint4*)&A[(long long)(bm + row) * lda + k0 + kc * 8];
        }
        #pragma unroll
        for (int i = 0; i < BN/64; i++) {
            const int c = tid + i * 256, row = c >> 2, kc = c & 3;
            bv[i] = *(const uint4*)&B[(long long)(bn + row) * ldb + k0 + kc * 8];
        }
        if (k0) __syncthreads();
        #pragma unroll
        for (int i = 0; i < 2; i++) {
            const int c = tid + i * 256, row = c >> 2, kc = c & 3;
            *(uint4*)&As[row][kc * 8] = av[i];
        }
        #pragma unroll
        for (int i = 0; i < BN/64; i++) {
            const int c = tid + i * 256, row = c >> 2, kc = c & 3;
            *(uint4*)&Bs[row][kc * 8] = bv[i];
        }
        __syncthreads();

        #pragma unroll
        for (int ks = 0; ks < 32; ks += 16) {
            uint32_t af[2][4], bf[BN/16][2];
            #pragma unroll
            for (int i = 0; i < 2; i++) {
                const int r0 = wm + 16 * i + g;
                af[i][0] = *(const uint32_t*)&As[r0    ][ks + 2 * t];
                af[i][1] = *(const uint32_t*)&As[r0 + 8][ks + 2 * t];
                af[i][2] = *(const uint32_t*)&As[r0    ][ks + 2 * t + 8];
                af[i][3] = *(const uint32_t*)&As[r0 + 8][ks + 2 * t + 8];
            }
            #pragma unroll
            for (int j = 0; j < NF; j++) {
                const int cn = wn + 8 * j + g;
                bf[j][0] = *(const uint32_t*)&Bs[cn][ks + 2 * t];
                bf[j][1] = *(const uint32_t*)&Bs[cn][ks + 2 * t + 8];
            }
            #pragma unroll
            for (int i = 0; i < 2; i++)
                #pragma unroll
                for (int j = 0; j < NF; j++)
                    mma_f16(acc[i][j], af[i], bf[j]);
        }
    }

    // epilogue: thread holds rows (bm+wm+16i+g, +8), cols (bn+wn+8j+2t, +1)
    #pragma unroll
    for (int i = 0; i < 2; i++) {
        const long long r0 = bm + wm + 16*i + g;
        const long long r1 = r0 + 8;
        float w0 = 0.f, w1 = 0.f;
        if (EPI == 4) { w0 = wvec[r0 * PATHS + z]; w1 = wvec[r1 * PATHS + z]; }
        #pragma unroll
        for (int j = 0; j < NF; j++) {
            const int col = bn + wn + 8*j + 2*t;
            const float bx = bias[col], by = bias[col + 1];
            float v0 = acc[i][j][0] + bx, v1 = acc[i][j][1] + by;   // row r0
            float v2 = acc[i][j][2] + bx, v3 = acc[i][j][3] + by;   // row r1
            if (EPI == 1) {
                float2 q0 = *(const float2*)&res[r0 * ldres + col];
                float2 q1 = *(const float2*)&res[r1 * ldres + col];
                v0 += q0.x; v1 += q0.y; v2 += q1.x; v3 += q1.y;
            }
            if (EPI == 2) { v0 = fmaxf(v0,0.f); v1 = fmaxf(v1,0.f); v2 = fmaxf(v2,0.f); v3 = fmaxf(v3,0.f); }
            if (EPI == 3) { v0 = gelu_tanh(v0); v1 = gelu_tanh(v1); v2 = gelu_tanh(v2); v3 = gelu_tanh(v3); }
            if (EPI == 4) {
                float2 q0 = *(const float2*)&res[r0 * ldres + col];
                float2 q1 = *(const float2*)&res[r1 * ldres + col];
                v0 = q0.x + v0 * w0; v1 = q0.y + v1 * w0;
                v2 = q1.x + v2 * w1; v3 = q1.y + v3 * w1;
            }
            if (sizeof(CT) == 4) {
                *(float2*)&((float*)C)[r0 * ldc + col] = make_float2(v0, v1);
                *(float2*)&((float*)C)[r1 * ldc + col] = make_float2(v2, v3);
            } else {
                *(half2*)&((__half*)C)[r0 * ldc + col] = __floats2half2_rn(v0, v1);
                *(half2*)&((__half*)C)[r1 * ldc + col] = __floats2half2_rn(v2, v3);
            }
        }
    }
}

// ---------------- flash attention: 64 q-rows per block, Dh=64 ----------------
__global__ __launch_bounds__(256) void attn_kernel(
    const float* __restrict__ qkv, __half* __restrict__ ctx)
{
    const int qb = blockIdx.x;     // 0..15 (q tile)
    const int h  = blockIdx.y;     // head
    const int b  = blockIdx.z;     // batch
    const float* base = qkv + (long long)b * S_LEN * 3 * HDIM;

    __shared__ __align__(16) float Qs[64][64];   // [d][qr], pre-scaled
    __shared__ __align__(16) float KP[64][64];   // K as [d][kc], then P as [kc][qr]
    __shared__ __align__(16) float Vs[64][64];   // [kv][d]

    const int tid = threadIdx.x;
    const int tx = tid & 15, ty = tid >> 4;

    for (int i = tid; i < 64 * 16; i += 256) {
        int qr = i >> 4, d4 = (i & 15) * 4;
        float4 v = *(const float4*)&base[(long long)(qb * 64 + qr) * (3 * HDIM) + h * DHEAD + d4];
        Qs[d4+0][qr] = v.x * 0.125f; Qs[d4+1][qr] = v.y * 0.125f;
        Qs[d4+2][qr] = v.z * 0.125f; Qs[d4+3][qr] = v.w * 0.125f;
    }

    float m[4], l[4], o[4][4];
    #pragma unroll
    for (int i = 0; i < 4; i++) {
        m[i] = -1e30f; l[i] = 0.f;
        #pragma unroll
        for (int j = 0; j < 4; j++) o[i][j] = 0.f;
    }

    for (int kb = 0; kb <= qb; kb++) {
        __syncthreads();
        for (int i = tid; i < 64 * 16; i += 256) {
            int kc = i >> 4, d4 = (i & 15) * 4;
            long long rowoff = (long long)(kb * 64 + kc) * (3 * HDIM) + h * DHEAD + d4;
            float4 kv = *(const float4*)&base[rowoff + HDIM];
            KP[d4+0][kc] = kv.x; KP[d4+1][kc] = kv.y; KP[d4+2][kc] = kv.z; KP[d4+3][kc] = kv.w;
            float4 vv = *(const float4*)&base[rowoff + 2 * HDIM];
            *(float4*)&Vs[kc][d4] = vv;
        }
        __syncthreads();

        float s[4][4];
        #pragma unroll
        for (int i = 0; i < 4; i++)
            #pragma unroll
            for (int j = 0; j < 4; j++) s[i][j] = 0.f;
        #pragma unroll 16
        for (int kk = 0; kk < 64; kk++) {
            float4 aq = *(const float4*)&Qs[kk][ty * 4];
            float4 bk = *(const float4*)&KP[kk][tx * 4];
            float ar[4] = {aq.x, aq.y, aq.z, aq.w};
            float br[4] = {bk.x, bk.y, bk.z, bk.w};
            #pragma unroll
            for (int i = 0; i < 4; i++)
                #pragma unroll
                for (int j = 0; j < 4; j++)
                    s[i][j] += ar[i] * br[j];
        }

        if (kb == qb) {
            #pragma unroll
            for (int i = 0; i < 4; i++) {
                int qg = ty * 4 + i;
                #pragma unroll
                for (int j = 0; j < 4; j++)
                    if (tx * 4 + j > qg) s[i][j] = -1e9f;
            }
        }

        #pragma unroll
        for (int i = 0; i < 4; i++) {
            float rm = fmaxf(fmaxf(s[i][0], s[i][1]), fmaxf(s[i][2], s[i][3]));
            #pragma unroll
            for (int off = 1; off < 16; off <<= 1)
                rm = fmaxf(rm, __shfl_xor_sync(0xffffffffu, rm, off, 16));
            float mnew = fmaxf(m[i], rm);
            float scale = __expf(m[i] - mnew);
            m[i] = mnew;
            float rsum = 0.f;
            #pragma unroll
            for (int j = 0; j < 4; j++) {
                float p = __expf(s[i][j] - mnew);
                s[i][j] = p; rsum += p;
            }
            #pragma unroll
            for (int off = 1; off < 16; off <<= 1)
                rsum += __shfl_xor_sync(0xffffffffu, rsum, off, 16);
            l[i] = l[i] * scale + rsum;
            #pragma unroll
            for (int j = 0; j < 4; j++) o[i][j] *= scale;
        }

        __syncthreads();
        #pragma unroll
        for (int i = 0; i < 4; i++)
            #pragma unroll
            for (int j = 0; j < 4; j++)
                KP[tx * 4 + j][ty * 4 + i] = s[i][j];
        __syncthreads();

        #pragma unroll 16
        for (int kk = 0; kk < 64; kk++) {
            float4 ap = *(const float4*)&KP[kk][ty * 4];
            float4 bv = *(const float4*)&Vs[kk][tx * 4];
            float ar[4] = {ap.x, ap.y, ap.z, ap.w};
            float br[4] = {bv.x, bv.y, bv.z, bv.w};
            #pragma unroll
            for (int i = 0; i < 4; i++)
                #pragma unroll
                for (int j = 0; j < 4; j++)
                    o[i][j] += ar[i] * br[j];
        }
    }

    #pragma unroll
    for (int i = 0; i < 4; i++) {
        float inv = 1.0f / l[i];
        long long t = (long long)b * S_LEN + qb * 64 + ty * 4 + i;
        *(half2*)&ctx[t * HDIM + h * DHEAD + tx * 4]     = __floats2half2_rn(o[i][0] * inv, o[i][1] * inv);
        *(half2*)&ctx[t * HDIM + h * DHEAD + tx * 4 + 2] = __floats2half2_rn(o[i][2] * inv, o[i][3] * inv);
    }
}

// ---------------- router: GEMV(16x256) + softmax + top-4 + renorm ------------
__global__ __launch_bounds__(128) void router_kernel(
    const float* __restrict__ r1, const float* __restrict__ Wr2,
    const float* __restrict__ br2, float* __restrict__ wout)
{
    int t = blockIdx.x;
    int tid = threadIdx.x;
    int p = tid >> 3, lane8 = tid & 7;

    const float4* a4 = (const float4*)(r1 + (long long)t * 256);
    const float4* w4 = (const float4*)(Wr2 + (long long)p * 256);
    float s = 0.f;
    #pragma unroll
    for (int j = 0; j < 8; j++) {
        float4 av = a4[lane8 * 8 + j];
        float4 wv = w4[lane8 * 8 + j];
        s += av.x * wv.x + av.y * wv.y + av.z * wv.z + av.w * wv.w;
    }
    #pragma unroll
    for (int o = 1; o < 8; o <<= 1) s += __shfl_xor_sync(0xffffffffu, s, o, 8);

    __shared__ float rv[16];
    if (lane8 == 0) rv[p] = s + br2[p];
    __syncthreads();

    if (tid == 0) {
        float pr[16];
        float vmax = rv[0];
        #pragma unroll
        for (int i = 1; i < 16; i++) vmax = fmaxf(vmax, rv[i]);
        float sum = 0.f;
        #pragma unroll
        for (int i = 0; i < 16; i++) { pr[i] = __expf(rv[i] - vmax); sum += pr[i]; }
        float inv = 1.0f / sum;
        #pragma unroll
        for (int i = 0; i < 16; i++) pr[i] *= inv;

        bool sel[16];
        #pragma unroll
        for (int i = 0; i < 16; i++) sel[i] = false;
        float ssum = 0.f;
        for (int k = 0; k < 4; k++) {
            int best = 0; float bv = -1.0f;
            for (int i = 0; i < 16; i++)
                if (!sel[i] && pr[i] > bv) { bv = pr[i]; best = i; }
            sel[best] = true; ssum += bv;
        }
        float dinv = 1.0f / (ssum + 1e-8f);
        for (int i = 0; i < 16; i++)
            wout[(long long)t * 16 + i] = sel[i] ? pr[i] * dinv : 0.f;
    }
}

// ---------------- launch ----------------
extern "C" void kernel_launch(void* const* d_in, const int* in_sizes, int n_in,
                              void* d_out, int out_size)
{
    const float* hidden = (const float*)d_in[0];
    const float* ln1w   = (const float*)d_in[1];
    const float* ln1b   = (const float*)d_in[2];
    const float* Wqkv   = (const float*)d_in[3];
    const float* bqkv   = (const float*)d_in[4];
    const float* Wo     = (const float*)d_in[5];
    const float* bo     = (const float*)d_in[6];
    const float* ln2w   = (const float*)d_in[7];
    const float* ln2b   = (const float*)d_in[8];
    const float* Wr1    = (const float*)d_in[9];
    const float* br1    = (const float*)d_in[10];
    const float* Wr2    = (const float*)d_in[11];
    const float* br2    = (const float*)d_in[12];
    const float* W1     = (const float*)d_in[13];
    const float* b1     = (const float*)d_in[14];
    const float* W2     = (const float*)d_in[15];
    const float* b2     = (const float*)d_in[16];
    float* out = (float*)d_out;

    float *qkv, *h, *r1, *wv;
    __half *xh, *ctxh, *x2h, *inth, *wqkvh, *woh, *wr1h, *w1h, *w2h;
    cudaGetSymbolAddress((void**)&qkv,   g_qkv_);
    cudaGetSymbolAddress((void**)&h,     g_h_);
    cudaGetSymbolAddress((void**)&r1,    g_r1_);
    cudaGetSymbolAddress((void**)&wv,    g_w_);
    cudaGetSymbolAddress((void**)&xh,    g_xh_);
    cudaGetSymbolAddress((void**)&ctxh,  g_ctxh_);
    cudaGetSymbolAddress((void**)&x2h,   g_x2h_);
    cudaGetSymbolAddress((void**)&inth,  g_inth_);
    cudaGetSymbolAddress((void**)&wqkvh, g_wqkvh_);
    cudaGetSymbolAddress((void**)&woh,   g_woh_);
    cudaGetSymbolAddress((void**)&wr1h,  g_wr1h_);
    cudaGetSymbolAddress((void**)&w1h,   g_w1h_);
    cudaGetSymbolAddress((void**)&w2h,   g_w2h_);

    // 0) weight conversions (fp32 -> fp16)
    f2h_kernel<<<3*HDIM*HDIM/1024, 256>>>(Wqkv, wqkvh, 3*HDIM*HDIM);
    f2h_kernel<<<HDIM*HDIM/1024,   256>>>(Wo,   woh,   HDIM*HDIM);
    f2h_kernel<<<256*HDIM/1024,    256>>>(Wr1,  wr1h,  256*HDIM);
    f2h_kernel<<<4096*HDIM/1024,   256>>>(W1,   w1h,   4096*HDIM);
    f2h_kernel<<<HDIM*4096/1024,   256>>>(W2,   w2h,   HDIM*4096);

    // 1) LN1 -> half
    ln_kernel<<<NTOK, 256>>>(hidden, ln1w, ln1b, xh);
    // 2) QKV = x @ Wqkv^T + bqkv            [4096 x 3072] fp32 out
    tgemm_kernel<0,128,float><<<dim3(3072/128, NTOK/128, 1), 256>>>(
        xh, HDIM, 0, wqkvh, HDIM, 0, qkv, 3*HDIM, 0, HDIM,
        bqkv, 0, nullptr, 0, 0, nullptr);
    // 3) causal attention -> ctx (half)
    attn_kernel<<<dim3(S_LEN/64, NHEADS, 4), 256>>>(qkv, ctxh);
    // 4) h = hidden + ctx @ Wo^T + bo       fp32 out
    tgemm_kernel<1,128,float><<<dim3(HDIM/128, NTOK/128, 1), 256>>>(
        ctxh, HDIM, 0, woh, HDIM, 0, h, HDIM, 0, HDIM,
        bo, 0, hidden, 0, HDIM, nullptr);
    // 5) LN2 -> half
    ln_kernel<<<NTOK, 256>>>(h, ln2w, ln2b, x2h);
    // 6) r1 = relu(x2 @ Wr1^T + br1)        [4096 x 256] fp32 out
    tgemm_kernel<2,128,float><<<dim3(256/128, NTOK/128, 1), 256>>>(
        x2h, HDIM, 0, wr1h, HDIM, 0, r1, 256, 0, HDIM,
        br1, 0, nullptr, 0, 0, nullptr);
    // 7) router logits + softmax + top-4 + renorm -> w [4096 x 16]
    router_kernel<<<NTOK, 128>>>(r1, Wr2, br2, wv);
    // 8) inter_p = gelu(x2_p @ W1b_p^T + b1_p)   (z = pathway), half out
    tgemm_kernel<3,128,__half><<<dim3(256/128, NTOK/128, PATHS), 256>>>(
        x2h, HDIM, 64, w1h, HDIM, (long long)256*HDIM + 64,
        inth, 256, (long long)NTOK*256, 64,
        b1, 256, nullptr, 0, 0, nullptr);
    // 9) out = h + (inter_p @ W2b_p^T + b2_p) * w[:,p]   (z = pathway) fp32 out
    tgemm_kernel<4,64,float><<<dim3(1, NTOK/128, PATHS), 256>>>(
        inth, 256, (long long)NTOK*256, w2h, 4096, (long long)64*4096 + 256,
        out, HDIM, 64, 256,
        b2, 64, h, 64, HDIM, wv);
}

// round 17
// speedup vs baseline: 2.8524x; 1.8948x over previous
#include <cuda_runtime.h>
#include <cuda_fp16.h>
#include <math.h>
#include <stdint.h>

#define S_LEN  1024
#define HDIM   1024
#define NTOK   4096            // B*S
#define NHEADS 16
#define DHEAD  64
#define PATHS  16

// ---------------- scratch (static __device__, no allocation) ----------------
__device__ float4 g_h_   [NTOK*HDIM/4];        // residual-1 out (fp32)
__device__ float4 g_r1_  [NTOK*256/4];         // router hidden (fp32)
__device__ float4 g_w_   [NTOK*PATHS/4];       // pathway weights (fp32)
__device__ __half g_qkvh_ [NTOK*3*HDIM];       // qkv (half)
__device__ __half g_xh_   [NTOK*HDIM];         // ln1 out (half)
__device__ __half g_ctxh_ [NTOK*HDIM];         // attention context (half)
__device__ __half g_x2h_  [NTOK*HDIM];         // ln2 out (half)
__device__ __half g_inth_ [(long long)PATHS*NTOK*256]; // pathway intermediates (half)
__device__ __half g_wqkvh_[3*HDIM*HDIM];
__device__ __half g_woh_  [HDIM*HDIM];
__device__ __half g_wr1h_ [256*HDIM];
__device__ __half g_w1h_  [4096*HDIM];
__device__ __half g_w2h_  [HDIM*4096];

// ---------------- fp32 -> fp16 convert ----------------
__global__ __launch_bounds__(256) void f2h_kernel(
    const float* __restrict__ s, __half* __restrict__ d, int n)
{
    int i = (blockIdx.x * 256 + threadIdx.x) * 4;
    if (i < n) {
        float4 v = *(const float4*)&s[i];
        *(half2*)&d[i]     = __floats2half2_rn(v.x, v.y);
        *(half2*)&d[i + 2] = __floats2half2_rn(v.z, v.w);
    }
}

// ---------------- LayerNorm (fp32 in, fp16 out) ----------------
__global__ __launch_bounds__(256) void ln_kernel(
    const float* __restrict__ x, const float* __restrict__ gamma,
    const float* __restrict__ beta, __half* __restrict__ y)
{
    long long row = blockIdx.x;
    const float* xr = x + row * HDIM;
    __half* yr = y + row * HDIM;
    int tid = threadIdx.x;

    float4 v = *(const float4*)&xr[tid * 4];
    float s  = v.x + v.y + v.z + v.w;
    float ss = v.x*v.x + v.y*v.y + v.z*v.z + v.w*v.w;
    #pragma unroll
    for (int o = 16; o; o >>= 1) {
        s  += __shfl_xor_sync(0xffffffffu, s,  o);
        ss += __shfl_xor_sync(0xffffffffu, ss, o);
    }
    __shared__ float rs[8], rss[8];
    int w = tid >> 5, ln = tid & 31;
    if (ln == 0) { rs[w] = s; rss[w] = ss; }
    __syncthreads();
    s = 0.f; ss = 0.f;
    #pragma unroll
    for (int i = 0; i < 8; i++) { s += rs[i]; ss += rss[i]; }

    float mean = s * (1.0f / HDIM);
    float var  = ss * (1.0f / HDIM) - mean * mean;
    float inv  = rsqrtf(var + 1e-5f);

    float4 g = *(const float4*)&gamma[tid * 4];
    float4 b = *(const float4*)&beta[tid * 4];
    float o0 = (v.x - mean) * inv * g.x + b.x;
    float o1 = (v.y - mean) * inv * g.y + b.y;
    float o2 = (v.z - mean) * inv * g.z + b.z;
    float o3 = (v.w - mean) * inv * g.w + b.w;
    *(half2*)&yr[tid * 4]     = __floats2half2_rn(o0, o1);
    *(half2*)&yr[tid * 4 + 2] = __floats2half2_rn(o2, o3);
}

// ---------------- fp16 MMA helpers ----------------
__device__ __forceinline__ void mma_f16(float c[4], const uint32_t a[4], const uint32_t b[2]) {
    asm volatile(
        "mma.sync.aligned.m16n8k16.row.col.f32.f16.f16.f32 "
        "{%0,%1,%2,%3}, {%4,%5,%6,%7}, {%8,%9}, {%0,%1,%2,%3};\n"
        : "+f"(c[0]), "+f"(c[1]), "+f"(c[2]), "+f"(c[3])
        : "r"(a[0]), "r"(a[1]), "r"(a[2]), "r"(a[3]), "r"(b[0]), "r"(b[1]));
}

__device__ __forceinline__ void ldmx2t(uint32_t b[2], uint32_t addr) {
    asm volatile("ldmatrix.sync.aligned.m8n8.x2.trans.shared.b16 {%0,%1}, [%2];\n"
                 : "=r"(b[0]), "=r"(b[1]) : "r"(addr));
}

__device__ __forceinline__ uint32_t packh2(float a, float b) {
    __half2 h = __floats2half2_rn(a, b);
    return *(uint32_t*)&h;
}

// ---------------- fp16 tensor-core GEMM: C = A[M,K] @ B[N,K]^T --------------
// BM=128, BN in {64,128}, BK=32, 256 threads (8 warps).
// EPI: 0=bias  1=bias+res  2=bias+relu  3=gelu(bias)  4=res + (acc+bias)*w[row,z]
__device__ __forceinline__ float gelu_tanh(float x) {
    float t = tanhf(0.7978845608028654f * (x + 0.044715f * x * x * x));
    return 0.5f * x * (1.0f + t);
}

template<int EPI, int BN, typename CT>
__global__ __launch_bounds__(256) void tgemm_kernel(
    const __half* __restrict__ A, int lda, long long aZ,
    const __half* __restrict__ B, int ldb, long long bZ,
    CT* __restrict__ C, int ldc, long long cZ,
    int K,
    const float* __restrict__ bias, int biasZ,
    const float* __restrict__ res, long long resZ, int ldres,
    const float* __restrict__ wvec)
{
    const int z = blockIdx.z;
    A += (long long)z * aZ;
    B += (long long)z * bZ;
    C += (long long)z * cZ;
    bias += (long long)z * biasZ;
    if (EPI == 1 || EPI == 4) res += (long long)z * resZ;

    __shared__ __align__(16) __half As[128][40];   // 128 x 32 data, stride 40
    __shared__ __align__(16) __half Bs[BN][40];

    const int tid  = threadIdx.x;
    const int warp = tid >> 5;
    const int lane = tid & 31;
    const int g = lane >> 2;               // groupID
    const int t = lane & 3;                // threadID_in_group
    const int wm = (warp & 3) * 32;        // warp m-offset
    const int wn = (warp >> 2) * (BN / 2); // warp n-offset
    const int bm = blockIdx.y * 128, bn = blockIdx.x * BN;
    const int NF = BN / 16;                // n-fragments per warp

    float acc[2][BN/16][4];
    #pragma unroll
    for (int i = 0; i < 2; i++)
        #pragma unroll
        for (int j = 0; j < NF; j++)
            #pragma unroll
            for (int q = 0; q < 4; q++) acc[i][j][q] = 0.f;

    for (int k0 = 0; k0 < K; k0 += 32) {
        uint4 av[2], bv[BN/64];
        #pragma unroll
        for (int i = 0; i < 2; i++) {
            const int c = tid + i * 256, row = c >> 2, kc = c & 3;
            av[i] = *(const uint4*)&A[(long long)(bm + row) * lda + k0 + kc * 8];
        }
        #pragma unroll
        for (int i = 0; i < BN/64; i++) {
            const int c = tid + i * 256, row = c >> 2, kc = c & 3;
            bv[i] = *(const uint4*)&B[(long long)(bn + row) * ldb + k0 + kc * 8];
        }
        if (k0) __syncthreads();
        #pragma unroll
        for (int i = 0; i < 2; i++) {
            const int c = tid + i * 256, row = c >> 2, kc = c & 3;
            *(uint4*)&As[row][kc * 8] = av[i];
        }
        #pragma unroll
        for (int i = 0; i < BN/64; i++) {
            const int c = tid + i * 256, row = c >> 2, kc = c & 3;
            *(uint4*)&Bs[row][kc * 8] = bv[i];
        }
        __syncthreads();

        #pragma unroll
        for (int ks = 0; ks < 32; ks += 16) {
            uint32_t af[2][4], bf[BN/16][2];
            #pragma unroll
            for (int i = 0; i < 2; i++) {
                const int r0 = wm + 16 * i + g;
                af[i][0] = *(const uint32_t*)&As[r0    ][ks + 2 * t];
                af[i][1] = *(const uint32_t*)&As[r0 + 8][ks + 2 * t];
                af[i][2] = *(const uint32_t*)&As[r0    ][ks + 2 * t + 8];
                af[i][3] = *(const uint32_t*)&As[r0 + 8][ks + 2 * t + 8];
            }
            #pragma unroll
            for (int j = 0; j < NF; j++) {
                const int cn = wn + 8 * j + g;
                bf[j][0] = *(const uint32_t*)&Bs[cn][ks + 2 * t];
                bf[j][1] = *(const uint32_t*)&Bs[cn][ks + 2 * t + 8];
            }
            #pragma unroll
            for (int i = 0; i < 2; i++)
                #pragma unroll
                for (int j = 0; j < NF; j++)
                    mma_f16(acc[i][j], af[i], bf[j]);
        }
    }

    // epilogue
    #pragma unroll
    for (int i = 0; i < 2; i++) {
        const long long r0 = bm + wm + 16*i + g;
        const long long r1 = r0 + 8;
        float w0 = 0.f, w1 = 0.f;
        if (EPI == 4) { w0 = wvec[r0 * PATHS + z]; w1 = wvec[r1 * PATHS + z]; }
        #pragma unroll
        for (int j = 0; j < NF; j++) {
            const int col = bn + wn + 8*j + 2*t;
            const float bx = bias[col], by = bias[col + 1];
            float v0 = acc[i][j][0] + bx, v1 = acc[i][j][1] + by;
            float v2 = acc[i][j][2] + bx, v3 = acc[i][j][3] + by;
            if (EPI == 1) {
                float2 q0 = *(const float2*)&res[r0 * ldres + col];
                float2 q1 = *(const float2*)&res[r1 * ldres + col];
                v0 += q0.x; v1 += q0.y; v2 += q1.x; v3 += q1.y;
            }
            if (EPI == 2) { v0 = fmaxf(v0,0.f); v1 = fmaxf(v1,0.f); v2 = fmaxf(v2,0.f); v3 = fmaxf(v3,0.f); }
            if (EPI == 3) { v0 = gelu_tanh(v0); v1 = gelu_tanh(v1); v2 = gelu_tanh(v2); v3 = gelu_tanh(v3); }
            if (EPI == 4) {
                float2 q0 = *(const float2*)&res[r0 * ldres + col];
                float2 q1 = *(const float2*)&res[r1 * ldres + col];
                v0 = q0.x + v0 * w0; v1 = q0.y + v1 * w0;
                v2 = q1.x + v2 * w1; v3 = q1.y + v3 * w1;
            }
            if (sizeof(CT) == 4) {
                *(float2*)&((float*)C)[r0 * ldc + col] = make_float2(v0, v1);
                *(float2*)&((float*)C)[r1 * ldc + col] = make_float2(v2, v3);
            } else {
                *(half2*)&((__half*)C)[r0 * ldc + col] = __floats2half2_rn(v0, v1);
                *(half2*)&((__half*)C)[r1 * ldc + col] = __floats2half2_rn(v2, v3);
            }
        }
    }
}

// ---------------- fp16 MMA flash attention: 128 q-rows/block, Dh=64 ---------
// 8 warps; warp w owns q rows [w*16, w*16+16). S and PV via m16n8k16.
// V kept row-major in smem; B-fragments via ldmatrix.x2.trans.
__global__ __launch_bounds__(256) void attn_kernel(
    const __half* __restrict__ qkv, __half* __restrict__ ctx)
{
    const int qb = blockIdx.x;     // 0..7 (128-row q tile)
    const int h  = blockIdx.y;     // head
    const int b  = blockIdx.z;     // batch
    const __half* base = qkv + (long long)b * S_LEN * 3 * HDIM;

    __shared__ __align__(16) __half Qs[128][72];
    __shared__ __align__(16) __half Ks[64][72];
    __shared__ __align__(16) __half Vs[64][72];

    const int tid  = threadIdx.x;
    const int warp = tid >> 5;
    const int lane = tid & 31;
    const int g = lane >> 2, t = lane & 3;

    // fill Q (pre-scaled by 1/sqrt(64) = 0.125)
    const __half2 sc = __float2half2_rn(0.125f);
    #pragma unroll
    for (int i = 0; i < 4; i++) {
        int idx = tid + i * 256, row = idx >> 3, ch = idx & 7;
        uint4 v = *(const uint4*)&base[(long long)(qb*128 + row) * (3*HDIM) + h*DHEAD + ch*8];
        __half2* p = (__half2*)&v;
        p[0] = __hmul2(p[0], sc); p[1] = __hmul2(p[1], sc);
        p[2] = __hmul2(p[2], sc); p[3] = __hmul2(p[3], sc);
        *(uint4*)&Qs[row][ch*8] = v;
    }
    __syncthreads();

    // Q fragments, register-resident for the whole KV loop
    uint32_t qf[4][4];
    const int r0 = warp * 16 + g;
    #pragma unroll
    for (int kk = 0; kk < 4; kk++) {
        qf[kk][0] = *(const uint32_t*)&Qs[r0    ][kk*16 + 2*t];
        qf[kk][1] = *(const uint32_t*)&Qs[r0 + 8][kk*16 + 2*t];
        qf[kk][2] = *(const uint32_t*)&Qs[r0    ][kk*16 + 2*t + 8];
        qf[kk][3] = *(const uint32_t*)&Qs[r0 + 8][kk*16 + 2*t + 8];
    }

    float m0 = -1e30f, m1 = -1e30f, l0 = 0.f, l1 = 0.f;
    float oa[8][4];
    #pragma unroll
    for (int j = 0; j < 8; j++)
        #pragma unroll
        for (int q = 0; q < 4; q++) oa[j][q] = 0.f;

    const int row_g0 = qb*128 + r0;
    const int row_g1 = row_g0 + 8;
    const int ntiles = 2*qb + 2;

    const uint32_t vs_base = (uint32_t)__cvta_generic_to_shared(&Vs[0][0]);

    for (int kb = 0; kb < ntiles; kb++) {
        __syncthreads();
        #pragma unroll
        for (int i = 0; i < 2; i++) {
            int idx = tid + i * 256, row = idx >> 3, ch = idx & 7;
            long long off = (long long)(kb*64 + row) * (3*HDIM) + h*DHEAD + ch*8;
            *(uint4*)&Ks[row][ch*8] = *(const uint4*)&base[off + HDIM];
            *(uint4*)&Vs[row][ch*8] = *(const uint4*)&base[off + 2*HDIM];
        }
        __syncthreads();

        // S = Q K^T  (16 x 64 per warp)
        float sf[8][4];
        #pragma unroll
        for (int j = 0; j < 8; j++)
            #pragma unroll
            for (int q = 0; q < 4; q++) sf[j][q] = 0.f;
        #pragma unroll
        for (int kk = 0; kk < 4; kk++) {
            #pragma unroll
            for (int j = 0; j < 8; j++) {
                uint32_t bq[2];
                bq[0] = *(const uint32_t*)&Ks[8*j + g][kk*16 + 2*t];
                bq[1] = *(const uint32_t*)&Ks[8*j + g][kk*16 + 2*t + 8];
                mma_f16(sf[j], qf[kk], bq);
            }
        }

        // causal mask
        if (kb*64 + 63 > row_g0) {
            #pragma unroll
            for (int j = 0; j < 8; j++) {
                const int c0 = kb*64 + 8*j + 2*t;
                if (c0     > row_g0) sf[j][0] = -1e9f;
                if (c0 + 1 > row_g0) sf[j][1] = -1e9f;
                if (c0     > row_g1) sf[j][2] = -1e9f;
                if (c0 + 1 > row_g1) sf[j][3] = -1e9f;
            }
        }

        // online softmax (rows g and g+8; stats across the 4-lane t-group)
        float pm0 = -1e30f, pm1 = -1e30f;
        #pragma unroll
        for (int j = 0; j < 8; j++) {
            pm0 = fmaxf(pm0, fmaxf(sf[j][0], sf[j][1]));
            pm1 = fmaxf(pm1, fmaxf(sf[j][2], sf[j][3]));
        }
        pm0 = fmaxf(pm0, __shfl_xor_sync(0xffffffffu, pm0, 1));
        pm0 = fmaxf(pm0, __shfl_xor_sync(0xffffffffu, pm0, 2));
        pm1 = fmaxf(pm1, __shfl_xor_sync(0xffffffffu, pm1, 1));
        pm1 = fmaxf(pm1, __shfl_xor_sync(0xffffffffu, pm1, 2));
        const float mn0 = fmaxf(m0, pm0), mn1 = fmaxf(m1, pm1);
        const float e0 = __expf(m0 - mn0), e1 = __expf(m1 - mn1);
        float ps0 = 0.f, ps1 = 0.f;
        #pragma unroll
        for (int j = 0; j < 8; j++) {
            sf[j][0] = __expf(sf[j][0] - mn0); ps0 += sf[j][0];
            sf[j][1] = __expf(sf[j][1] - mn0); ps0 += sf[j][1];
            sf[j][2] = __expf(sf[j][2] - mn1); ps1 += sf[j][2];
            sf[j][3] = __expf(sf[j][3] - mn1); ps1 += sf[j][3];
        }
        ps0 += __shfl_xor_sync(0xffffffffu, ps0, 1);
        ps0 += __shfl_xor_sync(0xffffffffu, ps0, 2);
        ps1 += __shfl_xor_sync(0xffffffffu, ps1, 1);
        ps1 += __shfl_xor_sync(0xffffffffu, ps1, 2);
        l0 = l0 * e0 + ps0; l1 = l1 * e1 + ps1;
        m0 = mn0; m1 = mn1;
        #pragma unroll
        for (int j = 0; j < 8; j++) {
            oa[j][0] *= e0; oa[j][1] *= e0;
            oa[j][2] *= e1; oa[j][3] *= e1;
        }

        // O += P V  (P repacked from S accumulators; V B-frags via ldmatrix.trans)
        #pragma unroll
        for (int kk = 0; kk < 4; kk++) {
            uint32_t pa[4];
            pa[0] = packh2(sf[2*kk][0],   sf[2*kk][1]);
            pa[1] = packh2(sf[2*kk][2],   sf[2*kk][3]);
            pa[2] = packh2(sf[2*kk+1][0], sf[2*kk+1][1]);
            pa[3] = packh2(sf[2*kk+1][2], sf[2*kk+1][3]);
            #pragma unroll
            for (int j = 0; j < 8; j++) {
                uint32_t bv[2];
                uint32_t addr = vs_base + ((kk*16 + (lane & 15)) * 72 + 8*j) * 2;
                ldmx2t(bv, addr);
                mma_f16(oa[j], pa, bv);
            }
        }
    }

    const float inv0 = 1.f / l0, inv1 = 1.f / l1;
    const long long t0 = (long long)b * S_LEN + qb*128 + r0;
    const long long t1 = t0 + 8;
    #pragma unroll
    for (int j = 0; j < 8; j++) {
        const int d = h*DHEAD + 8*j + 2*t;
        *(half2*)&ctx[t0 * HDIM + d] = __floats2half2_rn(oa[j][0]*inv0, oa[j][1]*inv0);
        *(half2*)&ctx[t1 * HDIM + d] = __floats2half2_rn(oa[j][2]*inv1, oa[j][3]*inv1);
    }
}

// ---------------- router: GEMV(16x256) + softmax + top-4 + renorm ------------
__global__ __launch_bounds__(128) void router_kernel(
    const float* __restrict__ r1, const float* __restrict__ Wr2,
    const float* __restrict__ br2, float* __restrict__ wout)
{
    int t = blockIdx.x;
    int tid = threadIdx.x;
    int p = tid >> 3, lane8 = tid & 7;

    const float4* a4 = (const float4*)(r1 + (long long)t * 256);
    const float4* w4 = (const float4*)(Wr2 + (long long)p * 256);
    float s = 0.f;
    #pragma unroll
    for (int j = 0; j < 8; j++) {
        float4 av = a4[lane8 * 8 + j];
        float4 wv = w4[lane8 * 8 + j];
        s += av.x * wv.x + av.y * wv.y + av.z * wv.z + av.w * wv.w;
    }
    #pragma unroll
    for (int o = 1; o < 8; o <<= 1) s += __shfl_xor_sync(0xffffffffu, s, o, 8);

    __shared__ float rv[16];
    if (lane8 == 0) rv[p] = s + br2[p];
    __syncthreads();

    if (tid == 0) {
        float pr[16];
        float vmax = rv[0];
        #pragma unroll
        for (int i = 1; i < 16; i++) vmax = fmaxf(vmax, rv[i]);
        float sum = 0.f;
        #pragma unroll
        for (int i = 0; i < 16; i++) { pr[i] = __expf(rv[i] - vmax); sum += pr[i]; }
        float inv = 1.0f / sum;
        #pragma unroll
        for (int i = 0; i < 16; i++) pr[i] *= inv;

        bool sel[16];
        #pragma unroll
        for (int i = 0; i < 16; i++) sel[i] = false;
        float ssum = 0.f;
        for (int k = 0; k < 4; k++) {
            int best = 0; float bv = -1.0f;
            for (int i = 0; i < 16; i++)
                if (!sel[i] && pr[i] > bv) { bv = pr[i]; best = i; }
            sel[best] = true; ssum += bv;
        }
        float dinv = 1.0f / (ssum + 1e-8f);
        for (int i = 0; i < 16; i++)
            wout[(long long)t * 16 + i] = sel[i] ? pr[i] * dinv : 0.f;
    }
}

// ---------------- launch ----------------
extern "C" void kernel_launch(void* const* d_in, const int* in_sizes, int n_in,
                              void* d_out, int out_size)
{
    const float* hidden = (const float*)d_in[0];
    const float* ln1w   = (const float*)d_in[1];
    const float* ln1b   = (const float*)d_in[2];
    const float* Wqkv   = (const float*)d_in[3];
    const float* bqkv   = (const float*)d_in[4];
    const float* Wo     = (const float*)d_in[5];
    const float* bo     = (const float*)d_in[6];
    const float* ln2w   = (const float*)d_in[7];
    const float* ln2b   = (const float*)d_in[8];
    const float* Wr1    = (const float*)d_in[9];
    const float* br1    = (const float*)d_in[10];
    const float* Wr2    = (const float*)d_in[11];
    const float* br2    = (const float*)d_in[12];
    const float* W1     = (const float*)d_in[13];
    const float* b1     = (const float*)d_in[14];
    const float* W2     = (const float*)d_in[15];
    const float* b2     = (const float*)d_in[16];
    float* out = (float*)d_out;

    float *h, *r1, *wv;
    __half *qkvh, *xh, *ctxh, *x2h, *inth, *wqkvh, *woh, *wr1h, *w1h, *w2h;
    cudaGetSymbolAddress((void**)&h,     g_h_);
    cudaGetSymbolAddress((void**)&r1,    g_r1_);
    cudaGetSymbolAddress((void**)&wv,    g_w_);
    cudaGetSymbolAddress((void**)&qkvh,  g_qkvh_);
    cudaGetSymbolAddress((void**)&xh,    g_xh_);
    cudaGetSymbolAddress((void**)&ctxh,  g_ctxh_);
    cudaGetSymbolAddress((void**)&x2h,   g_x2h_);
    cudaGetSymbolAddress((void**)&inth,  g_inth_);
    cudaGetSymbolAddress((void**)&wqkvh, g_wqkvh_);
    cudaGetSymbolAddress((void**)&woh,   g_woh_);
    cudaGetSymbolAddress((void**)&wr1h,  g_wr1h_);
    cudaGetSymbolAddress((void**)&w1h,   g_w1h_);
    cudaGetSymbolAddress((void**)&w2h,   g_w2h_);

    // 0) weight conversions (fp32 -> fp16)
    f2h_kernel<<<3*HDIM*HDIM/1024, 256>>>(Wqkv, wqkvh, 3*HDIM*HDIM);
    f2h_kernel<<<HDIM*HDIM/1024,   256>>>(Wo,   woh,   HDIM*HDIM);
    f2h_kernel<<<256*HDIM/1024,    256>>>(Wr1,  wr1h,  256*HDIM);
    f2h_kernel<<<4096*HDIM/1024,   256>>>(W1,   w1h,   4096*HDIM);
    f2h_kernel<<<HDIM*4096/1024,   256>>>(W2,   w2h,   HDIM*4096);

    // 1) LN1 -> half
    ln_kernel<<<NTOK, 256>>>(hidden, ln1w, ln1b, xh);
    // 2) QKV = x @ Wqkv^T + bqkv            [4096 x 3072] half out
    tgemm_kernel<0,128,__half><<<dim3(3072/128, NTOK/128, 1), 256>>>(
        xh, HDIM, 0, wqkvh, HDIM, 0, qkvh, 3*HDIM, 0, HDIM,
        bqkv, 0, nullptr, 0, 0, nullptr);
    // 3) causal attention (fp16 MMA) -> ctx (half)
    attn_kernel<<<dim3(S_LEN/128, NHEADS, 4), 256>>>(qkvh, ctxh);
    // 4) h = hidden + ctx @ Wo^T + bo       fp32 out
    tgemm_kernel<1,128,float><<<dim3(HDIM/128, NTOK/128, 1), 256>>>(
        ctxh, HDIM, 0, woh, HDIM, 0, h, HDIM, 0, HDIM,
        bo, 0, hidden, 0, HDIM, nullptr);
    // 5) LN2 -> half
    ln_kernel<<<NTOK, 256>>>(h, ln2w, ln2b, x2h);
    // 6) r1 = relu(x2 @ Wr1^T + br1)        [4096 x 256] fp32 out
    tgemm_kernel<2,128,float><<<dim3(256/128, NTOK/128, 1), 256>>>(
        x2h, HDIM, 0, wr1h, HDIM, 0, r1, 256, 0, HDIM,
        br1, 0, nullptr, 0, 0, nullptr);
    // 7) router logits + softmax + top-4 + renorm -> w [4096 x 16]
    router_kernel<<<NTOK, 128>>>(r1, Wr2, br2, wv);
    // 8) inter_p = gelu(x2_p @ W1b_p^T + b1_p)   (z = pathway), half out
    tgemm_kernel<3,128,__half><<<dim3(256/128, NTOK/128, PATHS), 256>>>(
        x2h, HDIM, 64, w1h, HDIM, (long long)256*HDIM + 64,
        inth, 256, (long long)NTOK*256, 64,
        b1, 256, nullptr, 0, 0, nullptr);
    // 9) out = h + (inter_p @ W2b_p^T + b2_p) * w[:,p]   (z = pathway) fp32 out
    tgemm_kernel<4,64,float><<<dim3(1, NTOK/128, PATHS), 256>>>(
        inth, 256, (long long)NTOK*256, w2h, 4096, (long long)64*4096 + 256,
        out, HDIM, 64, 256,
        b2, 64, h, 64, HDIM, wv);
}